// round 8
// baseline (speedup 1.0000x reference)
#include <cuda_runtime.h>
#include <math.h>
#include <stdint.h>

#define TT 128   // sequence length
#define DMM 32   // model dim

typedef uint32_t u32;

// ---- tf32 helpers ----
__device__ __forceinline__ float to_tf32(float x) {
    u32 u; asm("cvt.rna.tf32.f32 %0, %1;" : "=r"(u) : "f"(x)); return __uint_as_float(u);
}
// D += A(16x8,row) * B(8x8,col); tf32 in, f32 accum
__device__ __forceinline__ void mma8(float& d0, float& d1, float& d2, float& d3,
                                     u32 a0, u32 a1, u32 a2, u32 a3, u32 b0, u32 b1) {
    asm("mma.sync.aligned.m16n8k8.row.col.f32.tf32.tf32.f32 "
        "{%0,%1,%2,%3}, {%4,%5,%6,%7}, {%8,%9}, {%0,%1,%2,%3};"
        : "+f"(d0), "+f"(d1), "+f"(d2), "+f"(d3)
        : "r"(a0), "r"(a1), "r"(a2), "r"(a3), "r"(b0), "r"(b1));
}

// ---- smem layout (float offsets) ----
#define OFF_BO   0
#define OFF_B2   32
#define OFF_G1   64
#define OFF_BE1  96
#define OFF_G2   128
#define OFF_BE2  160
#define OFF_B1   192          // 128 floats
#define OFF_U    320
#define OFF_XN   (OFF_U)              // [128][36]: xn(tf32) -> AT -> ZN
#define OFF_WB   (OFF_U + 4608)       // Wqkv [32][104]=3328 -> Pbuf 4x[16][36] -> FFN chunk 4x[16][20]
#define OFF_Q    (OFF_U + 7936)       // Q [128][36] -> WoS [32][36] -> W1S [32][136]
#define OFF_K    (OFF_U + 12544)      // K [128][36] -> OS (Wo out / FFN out)
#define OFF_V    (OFF_U + 17152)      // V [128][36] -> W2S [128][36]
#define SM_FLOATS (OFF_U + 21760)

__device__ __forceinline__ void ln32(float (&v)[32], const float* g, const float* be) {
    float mu = 0.0f;
#pragma unroll
    for (int i = 0; i < 32; i++) mu += v[i];
    mu *= (1.0f / 32.0f);
    float var = 0.0f;
#pragma unroll
    for (int i = 0; i < 32; i++) { float d = v[i] - mu; var = fmaf(d, d, var); }
    var *= (1.0f / 32.0f);
    float rstd = rsqrtf(var + 1e-5f);
#pragma unroll
    for (int i = 0; i < 32; i++) v[i] = fmaf((v[i] - mu) * rstd, g[i], be[i]);
}

__global__ void __launch_bounds__(128) block_fused(
    const float* __restrict__ x,
    const float* __restrict__ Wq, const float* __restrict__ Wk, const float* __restrict__ Wv,
    const float* __restrict__ Wo, const float* __restrict__ bo,
    const float* __restrict__ W1, const float* __restrict__ b1,
    const float* __restrict__ W2, const float* __restrict__ b2,
    const float* __restrict__ g1, const float* __restrict__ be1,
    const float* __restrict__ g2, const float* __restrict__ be2,
    float* __restrict__ out)
{
    extern __shared__ float sm[];
    const int tid = threadIdx.x;
    const int t = tid;                 // one thread per token (scalar phases)
    const int lam = tid & 31, w = tid >> 5;
    const int lr = lam >> 2, lc = lam & 3;
    const size_t rowbase = ((size_t)blockIdx.x * TT + t) * DMM;

    // early x row load
    const float4* xrow = reinterpret_cast<const float4*>(x + rowbase);
    float4 xv4[8];
#pragma unroll
    for (int i = 0; i < 8; i++) xv4[i] = xrow[i];

    // ---- stage Wqkv [32 d][104] (cols: 0-31 Q, 32-63 K, 64-95 V; within: h*16+kk) ----
    for (int i = tid; i < 3072; i += 128) {
        int d = i / 96, j = i % 96;
        int sel = j >> 5, hj = (j >> 4) & 1, kk = j & 15;
        const float* Wsrc = (sel == 0) ? Wq : (sel == 1) ? Wk : Wv;
        sm[OFF_WB + d * 104 + j] = to_tf32(Wsrc[hj * 512 + d * 16 + kk]);
    }
    if (tid < 32) {
        sm[OFF_BO  + tid] = bo[tid];  sm[OFF_B2  + tid] = b2[tid];
        sm[OFF_G1  + tid] = g1[tid];  sm[OFF_BE1 + tid] = be1[tid];
        sm[OFF_G2  + tid] = g2[tid];  sm[OFF_BE2 + tid] = be2[tid];
    }
    sm[OFF_B1 + tid] = b1[tid];
    __syncthreads();

    // ---- LN1 (scalar, 1 row/thread); xn kept in regs for residual ----
    float xn[32];
#pragma unroll
    for (int i = 0; i < 8; i++) {
        xn[4*i+0] = xv4[i].x; xn[4*i+1] = xv4[i].y;
        xn[4*i+2] = xv4[i].z; xn[4*i+3] = xv4[i].w;
    }
    ln32(xn, sm + OFF_G1, sm + OFF_BE1);
    {
        float2* xr = reinterpret_cast<float2*>(&sm[OFF_XN + t * 36]);
#pragma unroll
        for (int p = 0; p < 16; p++)
            xr[p] = make_float2(to_tf32(xn[2*p]), to_tf32(xn[2*p+1]));
    }
    __syncthreads();

    // ================= QKV: [128,32] @ [32,96] =================
    {
#pragma unroll
        for (int mi = 0; mi < 2; mi++) {
            const int rb = (2 * w + mi) * 16;
            u32 A[4][4];
#pragma unroll
            for (int kt = 0; kt < 4; kt++) {
                A[kt][0] = __float_as_uint(sm[OFF_XN + (rb + lr)     * 36 + 8*kt + lc]);
                A[kt][1] = __float_as_uint(sm[OFF_XN + (rb + lr + 8) * 36 + 8*kt + lc]);
                A[kt][2] = __float_as_uint(sm[OFF_XN + (rb + lr)     * 36 + 8*kt + lc + 4]);
                A[kt][3] = __float_as_uint(sm[OFF_XN + (rb + lr + 8) * 36 + 8*kt + lc + 4]);
            }
#pragma unroll
            for (int nt = 0; nt < 12; nt++) {
                float c0 = 0.f, c1 = 0.f, c2 = 0.f, c3 = 0.f;
#pragma unroll
                for (int kt = 0; kt < 4; kt++) {
                    u32 b0 = __float_as_uint(sm[OFF_WB + (8*kt + lc)     * 104 + nt*8 + lr]);
                    u32 b1 = __float_as_uint(sm[OFF_WB + (8*kt + lc + 4) * 104 + nt*8 + lr]);
                    mma8(c0, c1, c2, c3, A[kt][0], A[kt][1], A[kt][2], A[kt][3], b0, b1);
                }
                const int dst  = OFF_Q + (nt >> 2) * 4608;   // Q / K / V
                const int colb = (nt & 3) * 8 + 2 * lc;
                *reinterpret_cast<float2*>(&sm[dst + (rb + lr)     * 36 + colb]) =
                    make_float2(to_tf32(c0), to_tf32(c1));
                *reinterpret_cast<float2*>(&sm[dst + (rb + lr + 8) * 36 + colb]) =
                    make_float2(to_tf32(c2), to_tf32(c3));
            }
        }
    }
    __syncthreads();

    // ================= causal attention (flash-style, per-warp (head, qt-set)) =================
    {
        const int h = w & 1;
        const int qs = w >> 1;
        float* Pb = sm + OFF_WB + w * 576;   // per-warp P chunk [16][36]
#pragma unroll
        for (int qi = 0; qi < 4; qi++) {
            // balanced sets: {0,3,4,7} and {1,2,5,6} -> 10 key-blocks each
            const int qt = qs ? ((qi == 0) ? 1 : (qi == 1) ? 2 : (qi == 2) ? 5 : 6)
                              : ((qi == 0) ? 0 : (qi == 1) ? 3 : (qi == 2) ? 4 : 7);
            u32 QA[2][4];
#pragma unroll
            for (int k2 = 0; k2 < 2; k2++) {
                QA[k2][0] = __float_as_uint(sm[OFF_Q + (qt*16 + lr)     * 36 + h*16 + 8*k2 + lc]);
                QA[k2][1] = __float_as_uint(sm[OFF_Q + (qt*16 + lr + 8) * 36 + h*16 + 8*k2 + lc]);
                QA[k2][2] = __float_as_uint(sm[OFF_Q + (qt*16 + lr)     * 36 + h*16 + 8*k2 + lc + 4]);
                QA[k2][3] = __float_as_uint(sm[OFF_Q + (qt*16 + lr + 8) * 36 + h*16 + 8*k2 + lc + 4]);
            }
            float o[2][4];
#pragma unroll
            for (int nv = 0; nv < 2; nv++)
#pragma unroll
                for (int c = 0; c < 4; c++) o[nv][c] = 0.f;
            float l_lo = 0.f, l_hi = 0.f;
            const int nkb = (qt >> 1) + 1;
            const int q_lo = qt * 16 + lr, q_hi = q_lo + 8;
            for (int kb = 0; kb < nkb; kb++) {
                // S = Q @ K^T for 32 keys
                float s[4][4];
#pragma unroll
                for (int ntk = 0; ntk < 4; ntk++) {
                    s[ntk][0] = s[ntk][1] = s[ntk][2] = s[ntk][3] = 0.f;
#pragma unroll
                    for (int k2 = 0; k2 < 2; k2++) {
                        u32 b0 = __float_as_uint(sm[OFF_K + (kb*32 + ntk*8 + lr) * 36 + h*16 + 8*k2 + lc]);
                        u32 b1 = __float_as_uint(sm[OFF_K + (kb*32 + ntk*8 + lr) * 36 + h*16 + 8*k2 + lc + 4]);
                        mma8(s[ntk][0], s[ntk][1], s[ntk][2], s[ntk][3],
                             QA[k2][0], QA[k2][1], QA[k2][2], QA[k2][3], b0, b1);
                    }
                }
                // mask + exp (no max-sub: |score| <~ 10) + row-sum partials + park P
#pragma unroll
                for (int ntk = 0; ntk < 4; ntk++) {
                    const int key0 = kb*32 + ntk*8 + 2*lc;
                    float p0 = (key0     <= q_lo) ? __expf(s[ntk][0]) : 0.f;
                    float p1 = (key0 + 1 <= q_lo) ? __expf(s[ntk][1]) : 0.f;
                    float p2 = (key0     <= q_hi) ? __expf(s[ntk][2]) : 0.f;
                    float p3 = (key0 + 1 <= q_hi) ? __expf(s[ntk][3]) : 0.f;
                    l_lo += p0 + p1;  l_hi += p2 + p3;
                    *reinterpret_cast<float2*>(&Pb[lr * 36 + ntk*8 + 2*lc]) =
                        make_float2(to_tf32(p0), to_tf32(p1));
                    *reinterpret_cast<float2*>(&Pb[(lr + 8) * 36 + ntk*8 + 2*lc]) =
                        make_float2(to_tf32(p2), to_tf32(p3));
                }
                __syncwarp();
                // O += P @ V
#pragma unroll
                for (int ks = 0; ks < 4; ks++) {
                    u32 pa0 = __float_as_uint(Pb[lr * 36       + ks*8 + lc]);
                    u32 pa1 = __float_as_uint(Pb[(lr + 8) * 36 + ks*8 + lc]);
                    u32 pa2 = __float_as_uint(Pb[lr * 36       + ks*8 + lc + 4]);
                    u32 pa3 = __float_as_uint(Pb[(lr + 8) * 36 + ks*8 + lc + 4]);
#pragma unroll
                    for (int nv = 0; nv < 2; nv++) {
                        u32 b0 = __float_as_uint(sm[OFF_V + (kb*32 + ks*8 + lc)     * 36 + h*16 + nv*8 + lr]);
                        u32 b1 = __float_as_uint(sm[OFF_V + (kb*32 + ks*8 + lc + 4) * 36 + h*16 + nv*8 + lr]);
                        mma8(o[nv][0], o[nv][1], o[nv][2], o[nv][3], pa0, pa1, pa2, pa3, b0, b1);
                    }
                }
                __syncwarp();
            }
            // finalize: quad-reduce row sums, divide, write AT (tf32) into XN slot
            l_lo += __shfl_xor_sync(0xffffffffu, l_lo, 1);
            l_lo += __shfl_xor_sync(0xffffffffu, l_lo, 2);
            l_hi += __shfl_xor_sync(0xffffffffu, l_hi, 1);
            l_hi += __shfl_xor_sync(0xffffffffu, l_hi, 2);
            const float ilo = __fdividef(1.f, l_lo), ihi = __fdividef(1.f, l_hi);
#pragma unroll
            for (int nv = 0; nv < 2; nv++) {
                *reinterpret_cast<float2*>(&sm[OFF_XN + (qt*16 + lr)     * 36 + h*16 + nv*8 + 2*lc]) =
                    make_float2(to_tf32(o[nv][0] * ilo), to_tf32(o[nv][1] * ilo));
                *reinterpret_cast<float2*>(&sm[OFF_XN + (qt*16 + lr + 8) * 36 + h*16 + nv*8 + 2*lc]) =
                    make_float2(to_tf32(o[nv][2] * ihi), to_tf32(o[nv][3] * ihi));
            }
        }
    }
    __syncthreads();

    // ---- stage Wo [32][36] tf32 into Q slot ----
    for (int i = tid; i < 1024; i += 128)
        sm[OFF_Q + (i >> 5) * 36 + (i & 31)] = to_tf32(Wo[i]);
    __syncthreads();

    // ================= Wo: [128,32] @ [32,32] -> OS (K slot) =================
    {
#pragma unroll
        for (int mi = 0; mi < 2; mi++) {
            const int rb = (2 * w + mi) * 16;
            u32 A[4][4];
#pragma unroll
            for (int kt = 0; kt < 4; kt++) {
                A[kt][0] = __float_as_uint(sm[OFF_XN + (rb + lr)     * 36 + 8*kt + lc]);
                A[kt][1] = __float_as_uint(sm[OFF_XN + (rb + lr + 8) * 36 + 8*kt + lc]);
                A[kt][2] = __float_as_uint(sm[OFF_XN + (rb + lr)     * 36 + 8*kt + lc + 4]);
                A[kt][3] = __float_as_uint(sm[OFF_XN + (rb + lr + 8) * 36 + 8*kt + lc + 4]);
            }
#pragma unroll
            for (int nt = 0; nt < 4; nt++) {
                float c0 = 0.f, c1 = 0.f, c2 = 0.f, c3 = 0.f;
#pragma unroll
                for (int kt = 0; kt < 4; kt++) {
                    u32 b0 = __float_as_uint(sm[OFF_Q + (8*kt + lc)     * 36 + nt*8 + lr]);
                    u32 b1 = __float_as_uint(sm[OFF_Q + (8*kt + lc + 4) * 36 + nt*8 + lr]);
                    mma8(c0, c1, c2, c3, A[kt][0], A[kt][1], A[kt][2], A[kt][3], b0, b1);
                }
                *reinterpret_cast<float2*>(&sm[OFF_K + (rb + lr)     * 36 + nt*8 + 2*lc]) =
                    make_float2(c0, c1);
                *reinterpret_cast<float2*>(&sm[OFF_K + (rb + lr + 8) * 36 + nt*8 + 2*lc]) =
                    make_float2(c2, c3);
            }
        }
    }
    __syncthreads();

    // ---- residual + LN2 (scalar); write ZN; stage W1/W2 ----
    float z[32];
    {
        const float* os = sm + OFF_K + t * 36;
#pragma unroll
        for (int c = 0; c < 32; c++) z[c] = xn[c] + os[c] + sm[OFF_BO + c];
        ln32(z, sm + OFF_G2, sm + OFF_BE2);
        float2* zr = reinterpret_cast<float2*>(&sm[OFF_XN + t * 36]);
#pragma unroll
        for (int p = 0; p < 16; p++)
            zr[p] = make_float2(to_tf32(z[2*p]), to_tf32(z[2*p+1]));
    }
    for (int i = tid; i < 4096; i += 128) {
        sm[OFF_Q + (i >> 7) * 136 + (i & 127)] = to_tf32(W1[i]);   // [32][136]
        sm[OFF_V + (i >> 5) * 36  + (i & 31)]  = to_tf32(W2[i]);   // [128][36]
    }
    __syncthreads();

    // ================= FFN via mma (fused relu through per-warp chunk) =================
    {
        float* ck = sm + OFF_WB + w * 320;   // [16][20]
        float c2f[2][4][4];
#pragma unroll
        for (int a = 0; a < 2; a++)
#pragma unroll
            for (int b = 0; b < 4; b++)
#pragma unroll
                for (int c = 0; c < 4; c++) c2f[a][b][c] = 0.f;
#pragma unroll
        for (int rtl = 0; rtl < 2; rtl++) {
            const int rb = w * 32 + rtl * 16;
            u32 A[4][4];
#pragma unroll
            for (int kt = 0; kt < 4; kt++) {
                A[kt][0] = __float_as_uint(sm[OFF_XN + (rb + lr)     * 36 + lc     + 8*kt]);
                A[kt][1] = __float_as_uint(sm[OFF_XN + (rb + lr + 8) * 36 + lc     + 8*kt]);
                A[kt][2] = __float_as_uint(sm[OFF_XN + (rb + lr)     * 36 + lc + 4 + 8*kt]);
                A[kt][3] = __float_as_uint(sm[OFF_XN + (rb + lr + 8) * 36 + lc + 4 + 8*kt]);
            }
#pragma unroll
            for (int g = 0; g < 8; g++) {
#pragma unroll
                for (int ntl = 0; ntl < 2; ntl++) {
                    const int nt = 2*g + ntl;
                    float h0 = 0.f, h1 = 0.f, h2 = 0.f, h3 = 0.f;
#pragma unroll
                    for (int kt = 0; kt < 4; kt++) {
                        u32 b0 = __float_as_uint(sm[OFF_Q + (lc     + 8*kt) * 136 + lr + 8*nt]);
                        u32 b1 = __float_as_uint(sm[OFF_Q + (lc + 4 + 8*kt) * 136 + lr + 8*nt]);
                        mma8(h0, h1, h2, h3, A[kt][0], A[kt][1], A[kt][2], A[kt][3], b0, b1);
                    }
                    const float bj0 = sm[OFF_B1 + 8*nt + 2*lc];
                    const float bj1 = sm[OFF_B1 + 8*nt + 2*lc + 1];
                    h0 = fmaxf(h0 + bj0, 0.f); h1 = fmaxf(h1 + bj1, 0.f);
                    h2 = fmaxf(h2 + bj0, 0.f); h3 = fmaxf(h3 + bj1, 0.f);
                    *reinterpret_cast<float2*>(ck + lr * 20       + 2*lc + 8*ntl) =
                        make_float2(to_tf32(h0), to_tf32(h1));
                    *reinterpret_cast<float2*>(ck + (lr + 8) * 20 + 2*lc + 8*ntl) =
                        make_float2(to_tf32(h2), to_tf32(h3));
                }
                __syncwarp();
#pragma unroll
                for (int ktl = 0; ktl < 2; ktl++) {
                    u32 p0 = __float_as_uint(ck[lr * 20       + lc     + 8*ktl]);
                    u32 p1 = __float_as_uint(ck[(lr + 8) * 20 + lc     + 8*ktl]);
                    u32 p2 = __float_as_uint(ck[lr * 20       + lc + 4 + 8*ktl]);
                    u32 p3 = __float_as_uint(ck[(lr + 8) * 20 + lc + 4 + 8*ktl]);
                    const int ktg = 2*g + ktl;
#pragma unroll
                    for (int nt2 = 0; nt2 < 4; nt2++) {
                        u32 b0 = __float_as_uint(sm[OFF_V + (lc     + 8*ktg) * 36 + lr + 8*nt2]);
                        u32 b1 = __float_as_uint(sm[OFF_V + (lc + 4 + 8*ktg) * 36 + lr + 8*nt2]);
                        mma8(c2f[rtl][nt2][0], c2f[rtl][nt2][1], c2f[rtl][nt2][2], c2f[rtl][nt2][3],
                             p0, p1, p2, p3, b0, b1);
                    }
                }
                __syncwarp();
            }
        }
        // scatter FFN output frags -> OS (K slot; prior contents consumed pre-sync)
#pragma unroll
        for (int rtl = 0; rtl < 2; rtl++) {
            const int rb = w * 32 + rtl * 16;
#pragma unroll
            for (int nt2 = 0; nt2 < 4; nt2++) {
                *reinterpret_cast<float2*>(&sm[OFF_K + (rb + lr)     * 36 + 8*nt2 + 2*lc]) =
                    make_float2(c2f[rtl][nt2][0], c2f[rtl][nt2][1]);
                *reinterpret_cast<float2*>(&sm[OFF_K + (rb + lr + 8) * 36 + 8*nt2 + 2*lc]) =
                    make_float2(c2f[rtl][nt2][2], c2f[rtl][nt2][3]);
            }
        }
    }
    __syncthreads();

    // ---- final residual + store ----
    {
        const float* r = sm + OFF_K + t * 36;
        float4* o4 = reinterpret_cast<float4*>(out + rowbase);
#pragma unroll
        for (int c4 = 0; c4 < 8; c4++)
            o4[c4] = make_float4(z[4*c4+0] + r[4*c4+0] + sm[OFF_B2 + 4*c4+0],
                                 z[4*c4+1] + r[4*c4+1] + sm[OFF_B2 + 4*c4+1],
                                 z[4*c4+2] + r[4*c4+2] + sm[OFF_B2 + 4*c4+2],
                                 z[4*c4+3] + r[4*c4+3] + sm[OFF_B2 + 4*c4+3]);
    }
}

extern "C" void kernel_launch(void* const* d_in, const int* in_sizes, int n_in,
                              void* d_out, int out_size) {
    const float* x   = (const float*)d_in[0];
    const float* Wq  = (const float*)d_in[1];
    const float* Wk  = (const float*)d_in[2];
    const float* Wv  = (const float*)d_in[3];
    const float* Wo  = (const float*)d_in[4];
    const float* bo  = (const float*)d_in[5];
    const float* W1  = (const float*)d_in[6];
    const float* b1  = (const float*)d_in[7];
    const float* W2  = (const float*)d_in[8];
    const float* b2  = (const float*)d_in[9];
    const float* g1  = (const float*)d_in[10];
    const float* be1 = (const float*)d_in[11];
    const float* g2  = (const float*)d_in[12];
    const float* be2 = (const float*)d_in[13];

    int B = in_sizes[0] / (TT * DMM);
    size_t shmem = SM_FLOATS * sizeof(float);
    cudaFuncSetAttribute(block_fused, cudaFuncAttributeMaxDynamicSharedMemorySize, (int)shmem);
    block_fused<<<B, 128, shmem>>>(x, Wq, Wk, Wv, Wo, bo, W1, b1, W2, b2,
                                   g1, be1, g2, be2, (float*)d_out);
}

// round 9
// speedup vs baseline: 2.5120x; 2.5120x over previous
#include <cuda_runtime.h>
#include <cuda_fp16.h>
#include <math.h>
#include <stdint.h>

#define TT 128
#define DMM 32

typedef uint32_t u32;

// ---- f32 region (float offsets) ----
#define F_BO   0
#define F_B2   32
#define F_G1   64
#define F_BE1  96
#define F_G2   128
#define F_BE2  160
#define F_B1   192          // 128 floats
#define F_OS   320          // [128][36] f32 (Wo out, then FFN out)
#define F_END  (320 + 128*36)
// ---- half region (half offsets), starts at byte 4*F_END ----
#define H_XN   0            // [128][40]  xn -> at -> zn
#define H_QS   5120         // [128][40]  Q  -> W1t[128][40]
#define H_KS   10240        // [128][40]  K  -> W2t[32][136]
#define H_VT   15360        // [32][136]  V^T (dv-major, keys contiguous)
#define H_WB   19712        // [96][40] WqkvT -> P 4x[16][40] -> WoT[32][40] -> chunks 4x[16][24]
#define H_END  (19712 + 3840)
#define SMEM_BYTES (4*F_END + 2*H_END)   // 66816

// D += A(16x16,row) * B(16x8,col), f16 in, f32 accum
__device__ __forceinline__ void mma16(float& d0, float& d1, float& d2, float& d3,
                                      u32 a0, u32 a1, u32 a2, u32 a3, u32 b0, u32 b1) {
    asm("mma.sync.aligned.m16n8k16.row.col.f32.f16.f16.f32 "
        "{%0,%1,%2,%3}, {%4,%5,%6,%7}, {%8,%9}, {%0,%1,%2,%3};"
        : "+f"(d0), "+f"(d1), "+f"(d2), "+f"(d3)
        : "r"(a0), "r"(a1), "r"(a2), "r"(a3), "r"(b0), "r"(b1));
}
__device__ __forceinline__ u32 h2(float lo, float hi) {
    __half2 v = __floats2half2_rn(lo, hi);
    return *reinterpret_cast<u32*>(&v);
}
__device__ __forceinline__ u32 ldh2(const __half* p) {
    return *reinterpret_cast<const u32*>(p);
}

__device__ __forceinline__ void ln32(float (&v)[32], const float* g, const float* be) {
    float mu = 0.0f;
#pragma unroll
    for (int i = 0; i < 32; i++) mu += v[i];
    mu *= (1.0f / 32.0f);
    float var = 0.0f;
#pragma unroll
    for (int i = 0; i < 32; i++) { float d = v[i] - mu; var = fmaf(d, d, var); }
    var *= (1.0f / 32.0f);
    float rstd = rsqrtf(var + 1e-5f);
#pragma unroll
    for (int i = 0; i < 32; i++) v[i] = fmaf((v[i] - mu) * rstd, g[i], be[i]);
}

__global__ void __launch_bounds__(128) block_fused(
    const float* __restrict__ x,
    const float* __restrict__ Wq, const float* __restrict__ Wk, const float* __restrict__ Wv,
    const float* __restrict__ Wo, const float* __restrict__ bo,
    const float* __restrict__ W1, const float* __restrict__ b1,
    const float* __restrict__ W2, const float* __restrict__ b2,
    const float* __restrict__ g1, const float* __restrict__ be1,
    const float* __restrict__ g2, const float* __restrict__ be2,
    float* __restrict__ out)
{
    extern __shared__ char smraw[];
    float* smf = reinterpret_cast<float*>(smraw);
    __half* smh = reinterpret_cast<__half*>(smraw + 4 * F_END);

    const int tid = threadIdx.x;
    const int t = tid;
    const int lam = tid & 31, w = tid >> 5;
    const int lr = lam >> 2, lc = lam & 3;    // g = lr (row-in-8), t' = lc
    const size_t rowbase = ((size_t)blockIdx.x * TT + t) * DMM;

    // early x row load
    const float4* xrow = reinterpret_cast<const float4*>(x + rowbase);
    float4 xv4[8];
#pragma unroll
    for (int i = 0; i < 8; i++) xv4[i] = xrow[i];

    // ---- stage Wqkv^T [96 n][40 k=d]; n: 0-31 Q, 32-63 K, 64-95 V; within: h*16+kk ----
    for (int i = tid; i < 3072; i += 128) {
        int n = i >> 5, d = i & 31;
        int sel = n >> 5, j = n & 31, hj = j >> 4, kk = j & 15;
        const float* Wsrc = (sel == 0) ? Wq : (sel == 1) ? Wk : Wv;
        smh[H_WB + n * 40 + d] = __float2half_rn(Wsrc[hj * 512 + d * 16 + kk]);
    }
    if (tid < 32) {
        smf[F_BO  + tid] = bo[tid];  smf[F_B2  + tid] = b2[tid];
        smf[F_G1  + tid] = g1[tid];  smf[F_BE1 + tid] = be1[tid];
        smf[F_G2  + tid] = g2[tid];  smf[F_BE2 + tid] = be2[tid];
    }
    smf[F_B1 + tid] = b1[tid];
    __syncthreads();

    // ---- LN1 (scalar); xn kept in regs; write half row to XN ----
    float xn[32];
#pragma unroll
    for (int i = 0; i < 8; i++) {
        xn[4*i+0] = xv4[i].x; xn[4*i+1] = xv4[i].y;
        xn[4*i+2] = xv4[i].z; xn[4*i+3] = xv4[i].w;
    }
    ln32(xn, smf + F_G1, smf + F_BE1);
    {
        u32* xr = reinterpret_cast<u32*>(smh + H_XN + t * 40);
#pragma unroll
        for (int p = 0; p < 16; p++) xr[p] = h2(xn[2*p], xn[2*p+1]);
    }
    __syncthreads();

    // ================= QKV: [128,32] @ [32,96] =================
    {
#pragma unroll
        for (int mi = 0; mi < 2; mi++) {
            const int rb = (2 * w + mi) * 16;
            u32 A[2][4];
#pragma unroll
            for (int kt = 0; kt < 2; kt++) {
                const __half* ab = smh + H_XN + 16 * kt + 2 * lc;
                A[kt][0] = ldh2(&ab[(rb + lr)     * 40]);
                A[kt][1] = ldh2(&ab[(rb + lr + 8) * 40]);
                A[kt][2] = ldh2(&ab[(rb + lr)     * 40 + 8]);
                A[kt][3] = ldh2(&ab[(rb + lr + 8) * 40 + 8]);
            }
#pragma unroll
            for (int nt = 0; nt < 12; nt++) {
                float c0 = 0.f, c1 = 0.f, c2 = 0.f, c3 = 0.f;
#pragma unroll
                for (int kt = 0; kt < 2; kt++) {
                    const __half* bb = smh + H_WB + (nt * 8 + lr) * 40 + 16 * kt + 2 * lc;
                    mma16(c0, c1, c2, c3, A[kt][0], A[kt][1], A[kt][2], A[kt][3],
                          ldh2(&bb[0]), ldh2(&bb[8]));
                }
                const int sel = nt >> 2, colb = (nt & 3) * 8 + 2 * lc;
                if (sel < 2) {
                    __half* dst = smh + (sel == 0 ? H_QS : H_KS);
                    *reinterpret_cast<u32*>(&dst[(rb + lr)     * 40 + colb]) = h2(c0, c1);
                    *reinterpret_cast<u32*>(&dst[(rb + lr + 8) * 40 + colb]) = h2(c2, c3);
                } else {  // V transposed: Vt[dv][token]
                    smh[H_VT + colb       * 136 + rb + lr]     = __float2half_rn(c0);
                    smh[H_VT + (colb + 1) * 136 + rb + lr]     = __float2half_rn(c1);
                    smh[H_VT + colb       * 136 + rb + lr + 8] = __float2half_rn(c2);
                    smh[H_VT + (colb + 1) * 136 + rb + lr + 8] = __float2half_rn(c3);
                }
            }
        }
    }
    __syncthreads();

    // ================= causal attention (flash-style; warp = (head, balanced qt-set)) =================
    {
        const int h = w & 1, qs = w >> 1;
        __half* Pb = smh + H_WB + w * 640;   // [16][40]
#pragma unroll
        for (int qi = 0; qi < 4; qi++) {
            const int qt = ((qs ? 0x6521 : 0x7430) >> (qi * 4)) & 0xF;  // {0,3,4,7}/{1,2,5,6}
            const __half* Qb = smh + H_QS + qt * 16 * 40 + h * 16 + 2 * lc;
            const u32 qa0 = ldh2(&Qb[lr * 40]);
            const u32 qa1 = ldh2(&Qb[(lr + 8) * 40]);
            const u32 qa2 = ldh2(&Qb[lr * 40 + 8]);
            const u32 qa3 = ldh2(&Qb[(lr + 8) * 40 + 8]);
            float o[2][4];
#pragma unroll
            for (int nv = 0; nv < 2; nv++)
#pragma unroll
                for (int c = 0; c < 4; c++) o[nv][c] = 0.f;
            float l_lo = 0.f, l_hi = 0.f;
            const int nkb = (qt >> 1) + 1;
            const int q_lo = qt * 16 + lr, q_hi = q_lo + 8;
            for (int kb = 0; kb < nkb; kb++) {
                float s[4][4];
#pragma unroll
                for (int ntk = 0; ntk < 4; ntk++) {
                    s[ntk][0] = s[ntk][1] = s[ntk][2] = s[ntk][3] = 0.f;
                    const __half* Kb = smh + H_KS + (kb*32 + ntk*8 + lr) * 40 + h*16 + 2*lc;
                    mma16(s[ntk][0], s[ntk][1], s[ntk][2], s[ntk][3],
                          qa0, qa1, qa2, qa3, ldh2(&Kb[0]), ldh2(&Kb[8]));
                }
#pragma unroll
                for (int ntk = 0; ntk < 4; ntk++) {
                    const int key0 = kb*32 + ntk*8 + 2*lc;
                    float p0 = (key0     <= q_lo) ? __expf(s[ntk][0]) : 0.f;
                    float p1 = (key0 + 1 <= q_lo) ? __expf(s[ntk][1]) : 0.f;
                    float p2 = (key0     <= q_hi) ? __expf(s[ntk][2]) : 0.f;
                    float p3 = (key0 + 1 <= q_hi) ? __expf(s[ntk][3]) : 0.f;
                    l_lo += p0 + p1;  l_hi += p2 + p3;
                    *reinterpret_cast<u32*>(&Pb[lr * 40       + ntk*8 + 2*lc]) = h2(p0, p1);
                    *reinterpret_cast<u32*>(&Pb[(lr + 8) * 40 + ntk*8 + 2*lc]) = h2(p2, p3);
                }
                __syncwarp();
#pragma unroll
                for (int ks = 0; ks < 2; ks++) {
                    const u32 pa0 = ldh2(&Pb[lr * 40       + 16*ks + 2*lc]);
                    const u32 pa1 = ldh2(&Pb[(lr + 8) * 40 + 16*ks + 2*lc]);
                    const u32 pa2 = ldh2(&Pb[lr * 40       + 16*ks + 2*lc + 8]);
                    const u32 pa3 = ldh2(&Pb[(lr + 8) * 40 + 16*ks + 2*lc + 8]);
#pragma unroll
                    for (int nv = 0; nv < 2; nv++) {
                        const __half* Vb = smh + H_VT + (h*16 + nv*8 + lr) * 136
                                         + kb*32 + ks*16 + 2*lc;
                        mma16(o[nv][0], o[nv][1], o[nv][2], o[nv][3],
                              pa0, pa1, pa2, pa3, ldh2(&Vb[0]), ldh2(&Vb[8]));
                    }
                }
                __syncwarp();
            }
            l_lo += __shfl_xor_sync(0xffffffffu, l_lo, 1);
            l_lo += __shfl_xor_sync(0xffffffffu, l_lo, 2);
            l_hi += __shfl_xor_sync(0xffffffffu, l_hi, 1);
            l_hi += __shfl_xor_sync(0xffffffffu, l_hi, 2);
            const float ilo = __fdividef(1.f, l_lo), ihi = __fdividef(1.f, l_hi);
#pragma unroll
            for (int nv = 0; nv < 2; nv++) {
                *reinterpret_cast<u32*>(&smh[H_XN + (qt*16 + lr)     * 40 + h*16 + nv*8 + 2*lc]) =
                    h2(o[nv][0] * ilo, o[nv][1] * ilo);
                *reinterpret_cast<u32*>(&smh[H_XN + (qt*16 + lr + 8) * 40 + h*16 + nv*8 + 2*lc]) =
                    h2(o[nv][2] * ihi, o[nv][3] * ihi);
            }
        }
    }
    __syncthreads();

    // ---- stage WoT [32 c][40 j], W1t [128 j][40 d], W2t [32 c][136 j] (Q/K/P-buf slots dead) ----
    for (int i = tid; i < 1024; i += 128) {
        int j = i >> 5, c = i & 31;
        smh[H_WB + c * 40 + j] = __float2half_rn(Wo[i]);      // i = j*32 + c
    }
    for (int i = tid; i < 4096; i += 128) {
        int d = i >> 7, j1 = i & 127;
        smh[H_QS + j1 * 40 + d] = __float2half_rn(W1[i]);     // i = d*128 + j1
        int j2 = i >> 5, c = i & 31;
        smh[H_KS + c * 136 + j2] = __float2half_rn(W2[i]);    // i = j2*32 + c
    }
    __syncthreads();

    // ================= Wo: [128,32] @ [32,32] -> OS (f32) =================
    {
#pragma unroll
        for (int mi = 0; mi < 2; mi++) {
            const int rb = (2 * w + mi) * 16;
            u32 A[2][4];
#pragma unroll
            for (int kt = 0; kt < 2; kt++) {
                const __half* ab = smh + H_XN + 16 * kt + 2 * lc;
                A[kt][0] = ldh2(&ab[(rb + lr)     * 40]);
                A[kt][1] = ldh2(&ab[(rb + lr + 8) * 40]);
                A[kt][2] = ldh2(&ab[(rb + lr)     * 40 + 8]);
                A[kt][3] = ldh2(&ab[(rb + lr + 8) * 40 + 8]);
            }
#pragma unroll
            for (int nt = 0; nt < 4; nt++) {
                float c0 = 0.f, c1 = 0.f, c2 = 0.f, c3 = 0.f;
#pragma unroll
                for (int kt = 0; kt < 2; kt++) {
                    const __half* bb = smh + H_WB + (nt*8 + lr) * 40 + 16*kt + 2*lc;
                    mma16(c0, c1, c2, c3, A[kt][0], A[kt][1], A[kt][2], A[kt][3],
                          ldh2(&bb[0]), ldh2(&bb[8]));
                }
                *reinterpret_cast<float2*>(&smf[F_OS + (rb + lr)     * 36 + nt*8 + 2*lc]) =
                    make_float2(c0, c1);
                *reinterpret_cast<float2*>(&smf[F_OS + (rb + lr + 8) * 36 + nt*8 + 2*lc]) =
                    make_float2(c2, c3);
            }
        }
    }
    __syncthreads();

    // ---- residual + LN2 (scalar); write ZN half into XN ----
    float z[32];
    {
        const float* os = smf + F_OS + t * 36;
#pragma unroll
        for (int c = 0; c < 32; c++) z[c] = xn[c] + os[c] + smf[F_BO + c];
        ln32(z, smf + F_G2, smf + F_BE2);
        u32* zr = reinterpret_cast<u32*>(smh + H_XN + t * 40);
#pragma unroll
        for (int p = 0; p < 16; p++) zr[p] = h2(z[2*p], z[2*p+1]);
    }
    __syncthreads();

    // ================= FFN: relu(ZN@W1+b1)@W2, fused via per-warp chunk =================
    {
        __half* ck = smh + H_WB + w * 384;   // [16][24]
        float cf[2][4][4];
#pragma unroll
        for (int a = 0; a < 2; a++)
#pragma unroll
            for (int b = 0; b < 4; b++)
#pragma unroll
                for (int c = 0; c < 4; c++) cf[a][b][c] = 0.f;
#pragma unroll
        for (int rtl = 0; rtl < 2; rtl++) {
            const int rb = w * 32 + rtl * 16;
            u32 A[2][4];
#pragma unroll
            for (int kt = 0; kt < 2; kt++) {
                const __half* ab = smh + H_XN + 16 * kt + 2 * lc;
                A[kt][0] = ldh2(&ab[(rb + lr)     * 40]);
                A[kt][1] = ldh2(&ab[(rb + lr + 8) * 40]);
                A[kt][2] = ldh2(&ab[(rb + lr)     * 40 + 8]);
                A[kt][3] = ldh2(&ab[(rb + lr + 8) * 40 + 8]);
            }
#pragma unroll
            for (int g = 0; g < 8; g++) {
#pragma unroll
                for (int ntl = 0; ntl < 2; ntl++) {
                    const int nt = 2*g + ntl;
                    float h0 = 0.f, h1 = 0.f, hh2 = 0.f, h3 = 0.f;
#pragma unroll
                    for (int kt = 0; kt < 2; kt++) {
                        const __half* bb = smh + H_QS + (nt*8 + lr) * 40 + 16*kt + 2*lc;
                        mma16(h0, h1, hh2, h3, A[kt][0], A[kt][1], A[kt][2], A[kt][3],
                              ldh2(&bb[0]), ldh2(&bb[8]));
                    }
                    const float bj0 = smf[F_B1 + nt*8 + 2*lc];
                    const float bj1 = smf[F_B1 + nt*8 + 2*lc + 1];
                    h0 = fmaxf(h0 + bj0, 0.f);  h1 = fmaxf(h1 + bj1, 0.f);
                    hh2 = fmaxf(hh2 + bj0, 0.f); h3 = fmaxf(h3 + bj1, 0.f);
                    *reinterpret_cast<u32*>(&ck[lr * 24       + ntl*8 + 2*lc]) = h2(h0, h1);
                    *reinterpret_cast<u32*>(&ck[(lr + 8) * 24 + ntl*8 + 2*lc]) = h2(hh2, h3);
                }
                __syncwarp();
                const u32 pa0 = ldh2(&ck[lr * 24       + 2*lc]);
                const u32 pa1 = ldh2(&ck[(lr + 8) * 24 + 2*lc]);
                const u32 pa2 = ldh2(&ck[lr * 24       + 2*lc + 8]);
                const u32 pa3 = ldh2(&ck[(lr + 8) * 24 + 2*lc + 8]);
#pragma unroll
                for (int nt2 = 0; nt2 < 4; nt2++) {
                    const __half* bb = smh + H_KS + (nt2*8 + lr) * 136 + g*16 + 2*lc;
                    mma16(cf[rtl][nt2][0], cf[rtl][nt2][1], cf[rtl][nt2][2], cf[rtl][nt2][3],
                          pa0, pa1, pa2, pa3, ldh2(&bb[0]), ldh2(&bb[8]));
                }
                __syncwarp();
            }
        }
        // scatter FFN output -> OS (f32)
#pragma unroll
        for (int rtl = 0; rtl < 2; rtl++) {
            const int rb = w * 32 + rtl * 16;
#pragma unroll
            for (int nt2 = 0; nt2 < 4; nt2++) {
                *reinterpret_cast<float2*>(&smf[F_OS + (rb + lr)     * 36 + nt2*8 + 2*lc]) =
                    make_float2(cf[rtl][nt2][0], cf[rtl][nt2][1]);
                *reinterpret_cast<float2*>(&smf[F_OS + (rb + lr + 8) * 36 + nt2*8 + 2*lc]) =
                    make_float2(cf[rtl][nt2][2], cf[rtl][nt2][3]);
            }
        }
    }
    __syncthreads();

    // ---- final residual + store ----
    {
        const float* r = smf + F_OS + t * 36;
        float4* o4 = reinterpret_cast<float4*>(out + rowbase);
#pragma unroll
        for (int c4 = 0; c4 < 8; c4++)
            o4[c4] = make_float4(z[4*c4+0] + r[4*c4+0] + smf[F_B2 + 4*c4+0],
                                 z[4*c4+1] + r[4*c4+1] + smf[F_B2 + 4*c4+1],
                                 z[4*c4+2] + r[4*c4+2] + smf[F_B2 + 4*c4+2],
                                 z[4*c4+3] + r[4*c4+3] + smf[F_B2 + 4*c4+3]);
    }
}

extern "C" void kernel_launch(void* const* d_in, const int* in_sizes, int n_in,
                              void* d_out, int out_size) {
    const float* x   = (const float*)d_in[0];
    const float* Wq  = (const float*)d_in[1];
    const float* Wk  = (const float*)d_in[2];
    const float* Wv  = (const float*)d_in[3];
    const float* Wo  = (const float*)d_in[4];
    const float* bo  = (const float*)d_in[5];
    const float* W1  = (const float*)d_in[6];
    const float* b1  = (const float*)d_in[7];
    const float* W2  = (const float*)d_in[8];
    const float* b2  = (const float*)d_in[9];
    const float* g1  = (const float*)d_in[10];
    const float* be1 = (const float*)d_in[11];
    const float* g2  = (const float*)d_in[12];
    const float* be2 = (const float*)d_in[13];

    int B = in_sizes[0] / (TT * DMM);
    cudaFuncSetAttribute(block_fused, cudaFuncAttributeMaxDynamicSharedMemorySize, SMEM_BYTES);
    block_fused<<<B, 128, SMEM_BYTES>>>(x, Wq, Wk, Wv, Wo, bo, W1, b1, W2, b2,
                                        g1, be1, g2, be2, (float*)d_out);
}

// round 10
// speedup vs baseline: 2.5814x; 1.0277x over previous
#include <cuda_runtime.h>
#include <cuda_fp16.h>
#include <math.h>
#include <stdint.h>

#define TT 128
#define DMM 32

typedef uint32_t u32;

// ---- f32 region (float offsets) ----
#define F_BO   0
#define F_B2   32
#define F_G1   64
#define F_BE1  96
#define F_G2   128
#define F_BE2  160
#define F_B1   192          // 128 floats
#define F_OS   320          // [128][36] f32 (Wo out, then FFN out)
#define F_END  (320 + 128*36)
// ---- half region (half offsets), starts at byte 4*F_END ----
#define H_XN   0            // [128][40]  xn -> at -> zn
#define H_QS   5120         // [128][40]  Q  -> W1t[128][40]
#define H_KS   10240        // [128][40]  K  -> W2t[32][136]
#define H_VT   15360        // [32][136]  V^T (dv-major, keys contiguous)
#define H_WB   19712        // [96][40] WqkvT -> P 4x[32][40] -> WoT[32][40] -> chunks 4x[32][24]
#define H_END  (19712 + 5120)
#define SMEM_BYTES (4*F_END + 2*H_END)   // 69376

__device__ __forceinline__ u32 sadd(const __half* p) {
    return static_cast<u32>(__cvta_generic_to_shared(p));
}
__device__ __forceinline__ void ldsm4(u32 (&r)[4], u32 a) {
    asm volatile("ldmatrix.sync.aligned.m8n8.x4.shared.b16 {%0,%1,%2,%3}, [%4];"
                 : "=r"(r[0]), "=r"(r[1]), "=r"(r[2]), "=r"(r[3]) : "r"(a));
}
// D += A(16x16,row) * B(16x8,col), f16 in, f32 accum
__device__ __forceinline__ void mma16a(float (&d)[4], const u32 (&a)[4], u32 b0, u32 b1) {
    asm("mma.sync.aligned.m16n8k16.row.col.f32.f16.f16.f32 "
        "{%0,%1,%2,%3}, {%4,%5,%6,%7}, {%8,%9}, {%0,%1,%2,%3};"
        : "+f"(d[0]), "+f"(d[1]), "+f"(d[2]), "+f"(d[3])
        : "r"(a[0]), "r"(a[1]), "r"(a[2]), "r"(a[3]), "r"(b0), "r"(b1));
}
__device__ __forceinline__ u32 h2(float lo, float hi) {
    __half2 v = __floats2half2_rn(lo, hi);
    return *reinterpret_cast<u32*>(&v);
}

// A m16k16 fragment (rows rb.., cols kb0.., stride S halves)
#define LDA(Areg, bp, rb, kb0, S) \
    ldsm4(Areg, sadd((bp) + ((rb) + (lam & 15)) * (S) + (kb0) + (lam >> 4) * 8))
// B: two n8-tiles (nb, nb+8) x k16 at kb0 -> {b0,b1}tile0, {b0,b1}tile1
#define LDB4(Breg, bp, nb, kb0, S) \
    ldsm4(Breg, sadd((bp) + ((nb) + ((lam >> 4) & 1) * 8 + (lam & 7)) * (S) + (kb0) + ((lam >> 3) & 1) * 8))

__device__ __forceinline__ void ln32(float (&v)[32], const float* g, const float* be) {
    float mu = 0.0f;
#pragma unroll
    for (int i = 0; i < 32; i++) mu += v[i];
    mu *= (1.0f / 32.0f);
    float var = 0.0f;
#pragma unroll
    for (int i = 0; i < 32; i++) { float d = v[i] - mu; var = fmaf(d, d, var); }
    var *= (1.0f / 32.0f);
    float rstd = rsqrtf(var + 1e-5f);
#pragma unroll
    for (int i = 0; i < 32; i++) v[i] = fmaf((v[i] - mu) * rstd, g[i], be[i]);
}

__global__ void __launch_bounds__(128) block_fused(
    const float* __restrict__ x,
    const float* __restrict__ Wq, const float* __restrict__ Wk, const float* __restrict__ Wv,
    const float* __restrict__ Wo, const float* __restrict__ bo,
    const float* __restrict__ W1, const float* __restrict__ b1,
    const float* __restrict__ W2, const float* __restrict__ b2,
    const float* __restrict__ g1, const float* __restrict__ be1,
    const float* __restrict__ g2, const float* __restrict__ be2,
    float* __restrict__ out)
{
    extern __shared__ char smraw[];
    float* smf = reinterpret_cast<float*>(smraw);
    __half* smh = reinterpret_cast<__half*>(smraw + 4 * F_END);

    const int tid = threadIdx.x;
    const int t = tid;
    const int lam = tid & 31, w = tid >> 5;
    const int lr = lam >> 2, lc = lam & 3;
    const size_t rowbase = ((size_t)blockIdx.x * TT + t) * DMM;

    // early x row load
    const float4* xrow = reinterpret_cast<const float4*>(x + rowbase);
    float4 xv4[8];
#pragma unroll
    for (int i = 0; i < 8; i++) xv4[i] = xrow[i];

    // ---- stage Wqkv^T [96 n][40 k=d]; n: 0-31 Q, 32-63 K, 64-95 V; within: h*16+kk ----
    for (int i = tid; i < 3072; i += 128) {
        int n = i >> 5, d = i & 31;
        int sel = n >> 5, j = n & 31, hj = j >> 4, kk = j & 15;
        const float* Wsrc = (sel == 0) ? Wq : (sel == 1) ? Wk : Wv;
        smh[H_WB + n * 40 + d] = __float2half_rn(Wsrc[hj * 512 + d * 16 + kk]);
    }
    if (tid < 32) {
        smf[F_BO  + tid] = bo[tid];  smf[F_B2  + tid] = b2[tid];
        smf[F_G1  + tid] = g1[tid];  smf[F_BE1 + tid] = be1[tid];
        smf[F_G2  + tid] = g2[tid];  smf[F_BE2 + tid] = be2[tid];
    }
    smf[F_B1 + tid] = b1[tid];
    __syncthreads();

    // ---- LN1 (scalar); xn kept in regs; write half row to XN ----
    float xn[32];
#pragma unroll
    for (int i = 0; i < 8; i++) {
        xn[4*i+0] = xv4[i].x; xn[4*i+1] = xv4[i].y;
        xn[4*i+2] = xv4[i].z; xn[4*i+3] = xv4[i].w;
    }
    ln32(xn, smf + F_G1, smf + F_BE1);
    {
        u32* xr = reinterpret_cast<u32*>(smh + H_XN + t * 40);
#pragma unroll
        for (int p = 0; p < 16; p++) xr[p] = h2(xn[2*p], xn[2*p+1]);
    }
    __syncthreads();

    // ================= QKV: [128,32] @ [32,96]; warp owns 32 rows (2 tiles) =================
    {
        const int rb = w * 32;
        u32 A[2][2][4];
        LDA(A[0][0], smh + H_XN, rb,      0,  40);
        LDA(A[0][1], smh + H_XN, rb,      16, 40);
        LDA(A[1][0], smh + H_XN, rb + 16, 0,  40);
        LDA(A[1][1], smh + H_XN, rb + 16, 16, 40);
#pragma unroll
        for (int np = 0; np < 6; np++) {
            float c[2][2][4];
#pragma unroll
            for (int a = 0; a < 2; a++)
#pragma unroll
                for (int b = 0; b < 2; b++)
#pragma unroll
                    for (int q = 0; q < 4; q++) c[a][b][q] = 0.f;
#pragma unroll
            for (int kt = 0; kt < 2; kt++) {
                u32 Bv[4];
                LDB4(Bv, smh + H_WB, np * 16, kt * 16, 40);
#pragma unroll
                for (int ti = 0; ti < 2; ti++) {
                    mma16a(c[ti][0], A[ti][kt], Bv[0], Bv[1]);
                    mma16a(c[ti][1], A[ti][kt], Bv[2], Bv[3]);
                }
            }
#pragma unroll
            for (int ti = 0; ti < 2; ti++)
#pragma unroll
            for (int ntl = 0; ntl < 2; ntl++) {
                const int nt = 2 * np + ntl;
                const int sel = nt >> 2, colb = (nt & 3) * 8 + 2 * lc;
                const int rr = rb + ti * 16;
                if (sel < 2) {
                    __half* dst = smh + (sel == 0 ? H_QS : H_KS);
                    *reinterpret_cast<u32*>(&dst[(rr + lr)     * 40 + colb]) = h2(c[ti][ntl][0], c[ti][ntl][1]);
                    *reinterpret_cast<u32*>(&dst[(rr + lr + 8) * 40 + colb]) = h2(c[ti][ntl][2], c[ti][ntl][3]);
                } else {  // V transposed: Vt[dv][token]
                    smh[H_VT + colb       * 136 + rr + lr]     = __float2half_rn(c[ti][ntl][0]);
                    smh[H_VT + (colb + 1) * 136 + rr + lr]     = __float2half_rn(c[ti][ntl][1]);
                    smh[H_VT + colb       * 136 + rr + lr + 8] = __float2half_rn(c[ti][ntl][2]);
                    smh[H_VT + (colb + 1) * 136 + rr + lr + 8] = __float2half_rn(c[ti][ntl][3]);
                }
            }
        }
    }
    __syncthreads();

    // ================= causal attention: warp = (head, equal-depth qt pair set) =================
    {
        const int h = w & 1, qs = w >> 1;
        __half* Pb = smh + H_WB + w * 1280;   // [32][40]
#pragma unroll
        for (int pi = 0; pi < 2; pi++) {
            // qs=0: pairs (0,1),(6,7); qs=1: pairs (2,3),(4,5). Same nkb within a pair.
            const int qt0 = qs ? (pi ? 4 : 2) : (pi ? 6 : 0);
            const int nkb = (qt0 >> 1) + 1;
            u32 QA[2][4];
            LDA(QA[0], smh + H_QS, qt0 * 16,       h * 16, 40);
            LDA(QA[1], smh + H_QS, (qt0 + 1) * 16, h * 16, 40);
            float o[2][2][4];
#pragma unroll
            for (int a = 0; a < 2; a++)
#pragma unroll
                for (int b = 0; b < 2; b++)
#pragma unroll
                    for (int q = 0; q < 4; q++) o[a][b][q] = 0.f;
            float l[2][2] = {{0.f, 0.f}, {0.f, 0.f}};
            for (int kb = 0; kb < nkb; kb++) {
                float s[2][4][4];
#pragma unroll
                for (int n2 = 0; n2 < 2; n2++) {
                    u32 Bv[4];
                    LDB4(Bv, smh + H_KS, kb * 32 + n2 * 16, h * 16, 40);
#pragma unroll
                    for (int ti = 0; ti < 2; ti++) {
                        s[ti][2*n2][0] = s[ti][2*n2][1] = s[ti][2*n2][2] = s[ti][2*n2][3] = 0.f;
                        s[ti][2*n2+1][0] = s[ti][2*n2+1][1] = s[ti][2*n2+1][2] = s[ti][2*n2+1][3] = 0.f;
                        mma16a(s[ti][2*n2],     QA[ti], Bv[0], Bv[1]);
                        mma16a(s[ti][2*n2 + 1], QA[ti], Bv[2], Bv[3]);
                    }
                }
#pragma unroll
                for (int ti = 0; ti < 2; ti++) {
                    const int q_lo = (qt0 + ti) * 16 + lr, q_hi = q_lo + 8;
#pragma unroll
                    for (int ntk = 0; ntk < 4; ntk++) {
                        const int key0 = kb * 32 + ntk * 8 + 2 * lc;
                        float p0 = (key0     <= q_lo) ? __expf(s[ti][ntk][0]) : 0.f;
                        float p1 = (key0 + 1 <= q_lo) ? __expf(s[ti][ntk][1]) : 0.f;
                        float p2 = (key0     <= q_hi) ? __expf(s[ti][ntk][2]) : 0.f;
                        float p3 = (key0 + 1 <= q_hi) ? __expf(s[ti][ntk][3]) : 0.f;
                        l[ti][0] += p0 + p1;  l[ti][1] += p2 + p3;
                        *reinterpret_cast<u32*>(&Pb[(ti*16 + lr)     * 40 + ntk*8 + 2*lc]) = h2(p0, p1);
                        *reinterpret_cast<u32*>(&Pb[(ti*16 + lr + 8) * 40 + ntk*8 + 2*lc]) = h2(p2, p3);
                    }
                }
                __syncwarp();
                u32 PA[2][2][4];
                LDA(PA[0][0], Pb, 0,  0,  40);
                LDA(PA[0][1], Pb, 0,  16, 40);
                LDA(PA[1][0], Pb, 16, 0,  40);
                LDA(PA[1][1], Pb, 16, 16, 40);
#pragma unroll
                for (int ks = 0; ks < 2; ks++) {
                    u32 Vv[4];
                    LDB4(Vv, smh + H_VT, h * 16, kb * 32 + ks * 16, 136);
#pragma unroll
                    for (int ti = 0; ti < 2; ti++) {
                        mma16a(o[ti][0], PA[ti][ks], Vv[0], Vv[1]);
                        mma16a(o[ti][1], PA[ti][ks], Vv[2], Vv[3]);
                    }
                }
                __syncwarp();
            }
#pragma unroll
            for (int ti = 0; ti < 2; ti++) {
                float ll = l[ti][0], lh = l[ti][1];
                ll += __shfl_xor_sync(0xffffffffu, ll, 1);
                ll += __shfl_xor_sync(0xffffffffu, ll, 2);
                lh += __shfl_xor_sync(0xffffffffu, lh, 1);
                lh += __shfl_xor_sync(0xffffffffu, lh, 2);
                const float il = __fdividef(1.f, ll), ih = __fdividef(1.f, lh);
                const int qr = (qt0 + ti) * 16;
#pragma unroll
                for (int nv = 0; nv < 2; nv++) {
                    *reinterpret_cast<u32*>(&smh[H_XN + (qr + lr)     * 40 + h*16 + nv*8 + 2*lc]) =
                        h2(o[ti][nv][0] * il, o[ti][nv][1] * il);
                    *reinterpret_cast<u32*>(&smh[H_XN + (qr + lr + 8) * 40 + h*16 + nv*8 + 2*lc]) =
                        h2(o[ti][nv][2] * ih, o[ti][nv][3] * ih);
                }
            }
        }
    }
    __syncthreads();

    // ---- stage WoT [32 c][40 j], W1t [128 j][40 d], W2t [32 c][136 j] ----
    for (int i = tid; i < 1024; i += 128) {
        int j = i >> 5, c = i & 31;
        smh[H_WB + c * 40 + j] = __float2half_rn(Wo[i]);      // i = j*32 + c
    }
    for (int i = tid; i < 4096; i += 128) {
        int d = i >> 7, j1 = i & 127;
        smh[H_QS + j1 * 40 + d] = __float2half_rn(W1[i]);     // i = d*128 + j1
        int j2 = i >> 5, c = i & 31;
        smh[H_KS + c * 136 + j2] = __float2half_rn(W2[i]);    // i = j2*32 + c
    }
    __syncthreads();

    // ================= Wo: [128,32] @ [32,32] -> OS (f32) =================
    {
        const int rb = w * 32;
        u32 A[2][2][4];
        LDA(A[0][0], smh + H_XN, rb,      0,  40);
        LDA(A[0][1], smh + H_XN, rb,      16, 40);
        LDA(A[1][0], smh + H_XN, rb + 16, 0,  40);
        LDA(A[1][1], smh + H_XN, rb + 16, 16, 40);
        float c[2][4][4];
#pragma unroll
        for (int a = 0; a < 2; a++)
#pragma unroll
            for (int b = 0; b < 4; b++)
#pragma unroll
                for (int q = 0; q < 4; q++) c[a][b][q] = 0.f;
#pragma unroll
        for (int kt = 0; kt < 2; kt++) {
#pragma unroll
            for (int n2 = 0; n2 < 2; n2++) {
                u32 Bv[4];
                LDB4(Bv, smh + H_WB, n2 * 16, kt * 16, 40);
#pragma unroll
                for (int ti = 0; ti < 2; ti++) {
                    mma16a(c[ti][2*n2],     A[ti][kt], Bv[0], Bv[1]);
                    mma16a(c[ti][2*n2 + 1], A[ti][kt], Bv[2], Bv[3]);
                }
            }
        }
#pragma unroll
        for (int ti = 0; ti < 2; ti++)
#pragma unroll
        for (int nt = 0; nt < 4; nt++) {
            const int rr = rb + ti * 16;
            *reinterpret_cast<float2*>(&smf[F_OS + (rr + lr)     * 36 + nt*8 + 2*lc]) =
                make_float2(c[ti][nt][0], c[ti][nt][1]);
            *reinterpret_cast<float2*>(&smf[F_OS + (rr + lr + 8) * 36 + nt*8 + 2*lc]) =
                make_float2(c[ti][nt][2], c[ti][nt][3]);
        }
    }
    __syncthreads();

    // ---- residual + LN2 (scalar); write ZN half into XN ----
    float z[32];
    {
        const float* os = smf + F_OS + t * 36;
#pragma unroll
        for (int c = 0; c < 32; c++) z[c] = xn[c] + os[c] + smf[F_BO + c];
        ln32(z, smf + F_G2, smf + F_BE2);
        u32* zr = reinterpret_cast<u32*>(smh + H_XN + t * 40);
#pragma unroll
        for (int p = 0; p < 16; p++) zr[p] = h2(z[2*p], z[2*p+1]);
    }
    __syncthreads();

    // ================= FFN: relu(ZN@W1+b1)@W2 fused via per-warp chunk =================
    {
        __half* ck = smh + H_WB + w * 768;   // [32][24]
        const int rb = w * 32;
        u32 A[2][2][4];
        LDA(A[0][0], smh + H_XN, rb,      0,  40);
        LDA(A[0][1], smh + H_XN, rb,      16, 40);
        LDA(A[1][0], smh + H_XN, rb + 16, 0,  40);
        LDA(A[1][1], smh + H_XN, rb + 16, 16, 40);
        float cf[2][4][4];
#pragma unroll
        for (int a = 0; a < 2; a++)
#pragma unroll
            for (int b = 0; b < 4; b++)
#pragma unroll
                for (int q = 0; q < 4; q++) cf[a][b][q] = 0.f;
#pragma unroll
        for (int g = 0; g < 8; g++) {
            float hv[2][2][4];
#pragma unroll
            for (int a = 0; a < 2; a++)
#pragma unroll
                for (int b = 0; b < 2; b++)
#pragma unroll
                    for (int q = 0; q < 4; q++) hv[a][b][q] = 0.f;
#pragma unroll
            for (int kt = 0; kt < 2; kt++) {
                u32 Bv[4];
                LDB4(Bv, smh + H_QS, g * 16, kt * 16, 40);
#pragma unroll
                for (int ti = 0; ti < 2; ti++) {
                    mma16a(hv[ti][0], A[ti][kt], Bv[0], Bv[1]);
                    mma16a(hv[ti][1], A[ti][kt], Bv[2], Bv[3]);
                }
            }
#pragma unroll
            for (int ti = 0; ti < 2; ti++)
#pragma unroll
            for (int ntl = 0; ntl < 2; ntl++) {
                const int nt = 2 * g + ntl;
                const float bj0 = smf[F_B1 + nt*8 + 2*lc];
                const float bj1 = smf[F_B1 + nt*8 + 2*lc + 1];
                float p0 = fmaxf(hv[ti][ntl][0] + bj0, 0.f);
                float p1 = fmaxf(hv[ti][ntl][1] + bj1, 0.f);
                float p2 = fmaxf(hv[ti][ntl][2] + bj0, 0.f);
                float p3 = fmaxf(hv[ti][ntl][3] + bj1, 0.f);
                *reinterpret_cast<u32*>(&ck[(ti*16 + lr)     * 24 + ntl*8 + 2*lc]) = h2(p0, p1);
                *reinterpret_cast<u32*>(&ck[(ti*16 + lr + 8) * 24 + ntl*8 + 2*lc]) = h2(p2, p3);
            }
            __syncwarp();
            u32 PA[2][4];
            LDA(PA[0], ck, 0,  0, 24);
            LDA(PA[1], ck, 16, 0, 24);
#pragma unroll
            for (int n2 = 0; n2 < 2; n2++) {
                u32 Bv[4];
                LDB4(Bv, smh + H_KS, n2 * 16, g * 16, 136);
#pragma unroll
                for (int ti = 0; ti < 2; ti++) {
                    mma16a(cf[ti][2*n2],     PA[ti], Bv[0], Bv[1]);
                    mma16a(cf[ti][2*n2 + 1], PA[ti], Bv[2], Bv[3]);
                }
            }
            __syncwarp();
        }
#pragma unroll
        for (int ti = 0; ti < 2; ti++)
#pragma unroll
        for (int nt2 = 0; nt2 < 4; nt2++) {
            const int rr = rb + ti * 16;
            *reinterpret_cast<float2*>(&smf[F_OS + (rr + lr)     * 36 + nt2*8 + 2*lc]) =
                make_float2(cf[ti][nt2][0], cf[ti][nt2][1]);
            *reinterpret_cast<float2*>(&smf[F_OS + (rr + lr + 8) * 36 + nt2*8 + 2*lc]) =
                make_float2(cf[ti][nt2][2], cf[ti][nt2][3]);
        }
    }
    __syncthreads();

    // ---- final residual + store ----
    {
        const float* r = smf + F_OS + t * 36;
        float4* o4 = reinterpret_cast<float4*>(out + rowbase);
#pragma unroll
        for (int c4 = 0; c4 < 8; c4++)
            o4[c4] = make_float4(z[4*c4+0] + r[4*c4+0] + smf[F_B2 + 4*c4+0],
                                 z[4*c4+1] + r[4*c4+1] + smf[F_B2 + 4*c4+1],
                                 z[4*c4+2] + r[4*c4+2] + smf[F_B2 + 4*c4+2],
                                 z[4*c4+3] + r[4*c4+3] + smf[F_B2 + 4*c4+3]);
    }
}

extern "C" void kernel_launch(void* const* d_in, const int* in_sizes, int n_in,
                              void* d_out, int out_size) {
    const float* x   = (const float*)d_in[0];
    const float* Wq  = (const float*)d_in[1];
    const float* Wk  = (const float*)d_in[2];
    const float* Wv  = (const float*)d_in[3];
    const float* Wo  = (const float*)d_in[4];
    const float* bo  = (const float*)d_in[5];
    const float* W1  = (const float*)d_in[6];
    const float* b1  = (const float*)d_in[7];
    const float* W2  = (const float*)d_in[8];
    const float* b2  = (const float*)d_in[9];
    const float* g1  = (const float*)d_in[10];
    const float* be1 = (const float*)d_in[11];
    const float* g2  = (const float*)d_in[12];
    const float* be2 = (const float*)d_in[13];

    int B = in_sizes[0] / (TT * DMM);
    cudaFuncSetAttribute(block_fused, cudaFuncAttributeMaxDynamicSharedMemorySize, SMEM_BYTES);
    block_fused<<<B, 128, SMEM_BYTES>>>(x, Wq, Wk, Wv, Wo, bo, W1, b1, W2, b2,
                                        g1, be1, g2, be2, (float*)d_out);
}

// round 11
// speedup vs baseline: 2.6128x; 1.0121x over previous
#include <cuda_runtime.h>
#include <cuda_fp16.h>
#include <math.h>
#include <stdint.h>

#define TT 128
#define DMM 32

typedef uint32_t u32;

// ---- f32 region (float offsets) ----
#define F_BO   0
#define F_B2   32
#define F_G1   64
#define F_BE1  96
#define F_G2   128
#define F_BE2  160
#define F_B1   192          // 128 floats
#define F_OS   320          // [128][36] f32 (Wo out, then FFN out)
#define F_END  (320 + 128*36)
// ---- half region (half offsets), starts at byte 4*F_END ----
#define H_XN   0            // [128][40]  xn -> at -> zn
#define H_QS   5120         // [128][40]  Q  -> W1t[128][40]
#define H_KS   10240        // [128][40]  K  -> W2t[32][136]
#define H_VT   15360        // [32][136]  V^T (dv-major, keys contiguous)
#define H_WB   19712        // [96][40] WqkvT -> P 8x[16][40] -> WoT[32][40] -> chunks 8x[16][24]
#define H_END  (19712 + 5120)
#define SMEM_BYTES (4*F_END + 2*H_END)   // 69376

__device__ __forceinline__ u32 sadd(const __half* p) {
    return static_cast<u32>(__cvta_generic_to_shared(p));
}
__device__ __forceinline__ void ldsm4(u32 (&r)[4], u32 a) {
    asm volatile("ldmatrix.sync.aligned.m8n8.x4.shared.b16 {%0,%1,%2,%3}, [%4];"
                 : "=r"(r[0]), "=r"(r[1]), "=r"(r[2]), "=r"(r[3]) : "r"(a));
}
// D += A(16x16,row) * B(16x8,col), f16 in, f32 accum
__device__ __forceinline__ void mma16a(float (&d)[4], const u32 (&a)[4], u32 b0, u32 b1) {
    asm("mma.sync.aligned.m16n8k16.row.col.f32.f16.f16.f32 "
        "{%0,%1,%2,%3}, {%4,%5,%6,%7}, {%8,%9}, {%0,%1,%2,%3};"
        : "+f"(d[0]), "+f"(d[1]), "+f"(d[2]), "+f"(d[3])
        : "r"(a[0]), "r"(a[1]), "r"(a[2]), "r"(a[3]), "r"(b0), "r"(b1));
}
__device__ __forceinline__ u32 h2(float lo, float hi) {
    __half2 v = __floats2half2_rn(lo, hi);
    return *reinterpret_cast<u32*>(&v);
}

// A m16k16 fragment (rows rb.., cols kb0.., stride S halves)
#define LDA(Areg, bp, rb, kb0, S) \
    ldsm4(Areg, sadd((bp) + ((rb) + (lam & 15)) * (S) + (kb0) + (lam >> 4) * 8))
// B: two n8-tiles (nb, nb+8) x k16 at kb0 -> {b0,b1}tile0, {b0,b1}tile1
#define LDB4(Breg, bp, nb, kb0, S) \
    ldsm4(Breg, sadd((bp) + ((nb) + ((lam >> 4) & 1) * 8 + (lam & 7)) * (S) + (kb0) + ((lam >> 3) & 1) * 8))

__device__ __forceinline__ void ln32(float (&v)[32], const float* g, const float* be) {
    float mu = 0.0f;
#pragma unroll
    for (int i = 0; i < 32; i++) mu += v[i];
    mu *= (1.0f / 32.0f);
    float var = 0.0f;
#pragma unroll
    for (int i = 0; i < 32; i++) { float d = v[i] - mu; var = fmaf(d, d, var); }
    var *= (1.0f / 32.0f);
    float rstd = rsqrtf(var + 1e-5f);
#pragma unroll
    for (int i = 0; i < 32; i++) v[i] = fmaf((v[i] - mu) * rstd, g[i], be[i]);
}

__global__ void __launch_bounds__(256, 3) block_fused(
    const float* __restrict__ x,
    const float* __restrict__ Wq, const float* __restrict__ Wk, const float* __restrict__ Wv,
    const float* __restrict__ Wo, const float* __restrict__ bo,
    const float* __restrict__ W1, const float* __restrict__ b1,
    const float* __restrict__ W2, const float* __restrict__ b2,
    const float* __restrict__ g1, const float* __restrict__ be1,
    const float* __restrict__ g2, const float* __restrict__ be2,
    float* __restrict__ out)
{
    extern __shared__ char smraw[];
    float* smf = reinterpret_cast<float*>(smraw);
    __half* smh = reinterpret_cast<__half*>(smraw + 4 * F_END);

    const int tid = threadIdx.x;
    const int t = tid;                       // token row for scalar phases (tid < 128)
    const int lam = tid & 31, w = tid >> 5;  // 8 warps
    const int lr = lam >> 2, lc = lam & 3;
    const size_t rowbase = ((size_t)blockIdx.x * TT + t) * DMM;

    // early x row load (rows 0..127 only)
    float4 xv4[8];
    if (t < TT) {
        const float4* xrow = reinterpret_cast<const float4*>(x + rowbase);
#pragma unroll
        for (int i = 0; i < 8; i++) xv4[i] = xrow[i];
    }

    // ---- stage Wqkv^T [96 n][40 k=d]; n: 0-31 Q, 32-63 K, 64-95 V; within: h*16+kk ----
    for (int i = tid; i < 3072; i += 256) {
        int n = i >> 5, d = i & 31;
        int sel = n >> 5, j = n & 31, hj = j >> 4, kk = j & 15;
        const float* Wsrc = (sel == 0) ? Wq : (sel == 1) ? Wk : Wv;
        smh[H_WB + n * 40 + d] = __float2half_rn(Wsrc[hj * 512 + d * 16 + kk]);
    }
    if (tid < 32) {
        smf[F_BO  + tid] = bo[tid];  smf[F_B2  + tid] = b2[tid];
        smf[F_G1  + tid] = g1[tid];  smf[F_BE1 + tid] = be1[tid];
        smf[F_G2  + tid] = g2[tid];  smf[F_BE2 + tid] = be2[tid];
    }
    if (tid < 128) smf[F_B1 + tid] = b1[tid];
    __syncthreads();

    // ---- LN1 (scalar, rows 0..127); xn kept in regs; write half row to XN ----
    float xn[32];
    if (t < TT) {
#pragma unroll
        for (int i = 0; i < 8; i++) {
            xn[4*i+0] = xv4[i].x; xn[4*i+1] = xv4[i].y;
            xn[4*i+2] = xv4[i].z; xn[4*i+3] = xv4[i].w;
        }
        ln32(xn, smf + F_G1, smf + F_BE1);
        u32* xr = reinterpret_cast<u32*>(smh + H_XN + t * 40);
#pragma unroll
        for (int p = 0; p < 16; p++) xr[p] = h2(xn[2*p], xn[2*p+1]);
    }
    __syncthreads();

    // ================= QKV: [128,32] @ [32,96]; warp owns 16 rows =================
    {
        const int rb = w * 16;
        u32 A[2][4];
        LDA(A[0], smh + H_XN, rb, 0,  40);
        LDA(A[1], smh + H_XN, rb, 16, 40);
#pragma unroll
        for (int np = 0; np < 6; np++) {
            float c[2][4];
#pragma unroll
            for (int b = 0; b < 2; b++)
#pragma unroll
                for (int q = 0; q < 4; q++) c[b][q] = 0.f;
#pragma unroll
            for (int kt = 0; kt < 2; kt++) {
                u32 Bv[4];
                LDB4(Bv, smh + H_WB, np * 16, kt * 16, 40);
                mma16a(c[0], A[kt], Bv[0], Bv[1]);
                mma16a(c[1], A[kt], Bv[2], Bv[3]);
            }
#pragma unroll
            for (int ntl = 0; ntl < 2; ntl++) {
                const int nt = 2 * np + ntl;
                const int sel = nt >> 2, colb = (nt & 3) * 8 + 2 * lc;
                if (sel < 2) {
                    __half* dst = smh + (sel == 0 ? H_QS : H_KS);
                    *reinterpret_cast<u32*>(&dst[(rb + lr)     * 40 + colb]) = h2(c[ntl][0], c[ntl][1]);
                    *reinterpret_cast<u32*>(&dst[(rb + lr + 8) * 40 + colb]) = h2(c[ntl][2], c[ntl][3]);
                } else {  // V transposed: Vt[dv][token]
                    smh[H_VT + colb       * 136 + rb + lr]     = __float2half_rn(c[ntl][0]);
                    smh[H_VT + (colb + 1) * 136 + rb + lr]     = __float2half_rn(c[ntl][1]);
                    smh[H_VT + colb       * 136 + rb + lr + 8] = __float2half_rn(c[ntl][2]);
                    smh[H_VT + (colb + 1) * 136 + rb + lr + 8] = __float2half_rn(c[ntl][3]);
                }
            }
        }
    }
    __syncthreads();

    // ================= causal attention: warp = (head, balanced qt pair {ws, 7-ws}) =================
    {
        const int h = w & 1, ws = w >> 1;
        __half* Pb = smh + H_WB + w * 640;   // [16][40]
#pragma unroll
        for (int qi = 0; qi < 2; qi++) {
            const int qt = qi ? (7 - ws) : ws;    // depths: 5/5/4/4 key-blocks per warp
            const int nkb = (qt >> 1) + 1;
            u32 QA[4];
            LDA(QA, smh + H_QS, qt * 16, h * 16, 40);
            float o[2][4];
#pragma unroll
            for (int b = 0; b < 2; b++)
#pragma unroll
                for (int q = 0; q < 4; q++) o[b][q] = 0.f;
            float l_lo = 0.f, l_hi = 0.f;
            const int q_lo = qt * 16 + lr, q_hi = q_lo + 8;
            for (int kb = 0; kb < nkb; kb++) {
                float s[4][4];
#pragma unroll
                for (int n2 = 0; n2 < 2; n2++) {
                    u32 Bv[4];
                    LDB4(Bv, smh + H_KS, kb * 32 + n2 * 16, h * 16, 40);
                    s[2*n2][0] = s[2*n2][1] = s[2*n2][2] = s[2*n2][3] = 0.f;
                    s[2*n2+1][0] = s[2*n2+1][1] = s[2*n2+1][2] = s[2*n2+1][3] = 0.f;
                    mma16a(s[2*n2],     QA, Bv[0], Bv[1]);
                    mma16a(s[2*n2 + 1], QA, Bv[2], Bv[3]);
                }
#pragma unroll
                for (int ntk = 0; ntk < 4; ntk++) {
                    const int key0 = kb * 32 + ntk * 8 + 2 * lc;
                    float p0 = (key0     <= q_lo) ? __expf(s[ntk][0]) : 0.f;
                    float p1 = (key0 + 1 <= q_lo) ? __expf(s[ntk][1]) : 0.f;
                    float p2 = (key0     <= q_hi) ? __expf(s[ntk][2]) : 0.f;
                    float p3 = (key0 + 1 <= q_hi) ? __expf(s[ntk][3]) : 0.f;
                    l_lo += p0 + p1;  l_hi += p2 + p3;
                    *reinterpret_cast<u32*>(&Pb[lr * 40       + ntk*8 + 2*lc]) = h2(p0, p1);
                    *reinterpret_cast<u32*>(&Pb[(lr + 8) * 40 + ntk*8 + 2*lc]) = h2(p2, p3);
                }
                __syncwarp();
                u32 PA[2][4];
                LDA(PA[0], Pb, 0, 0,  40);
                LDA(PA[1], Pb, 0, 16, 40);
#pragma unroll
                for (int ks = 0; ks < 2; ks++) {
                    u32 Vv[4];
                    LDB4(Vv, smh + H_VT, h * 16, kb * 32 + ks * 16, 136);
                    mma16a(o[0], PA[ks], Vv[0], Vv[1]);
                    mma16a(o[1], PA[ks], Vv[2], Vv[3]);
                }
                __syncwarp();
            }
            l_lo += __shfl_xor_sync(0xffffffffu, l_lo, 1);
            l_lo += __shfl_xor_sync(0xffffffffu, l_lo, 2);
            l_hi += __shfl_xor_sync(0xffffffffu, l_hi, 1);
            l_hi += __shfl_xor_sync(0xffffffffu, l_hi, 2);
            const float il = __fdividef(1.f, l_lo), ih = __fdividef(1.f, l_hi);
            const int qr = qt * 16;
#pragma unroll
            for (int nv = 0; nv < 2; nv++) {
                *reinterpret_cast<u32*>(&smh[H_XN + (qr + lr)     * 40 + h*16 + nv*8 + 2*lc]) =
                    h2(o[nv][0] * il, o[nv][1] * il);
                *reinterpret_cast<u32*>(&smh[H_XN + (qr + lr + 8) * 40 + h*16 + nv*8 + 2*lc]) =
                    h2(o[nv][2] * ih, o[nv][3] * ih);
            }
        }
    }
    __syncthreads();

    // ---- stage WoT [32 c][40 j], W1t [128 j][40 d], W2t [32 c][136 j] ----
    for (int i = tid; i < 1024; i += 256) {
        int j = i >> 5, c = i & 31;
        smh[H_WB + c * 40 + j] = __float2half_rn(Wo[i]);      // i = j*32 + c
    }
    for (int i = tid; i < 4096; i += 256) {
        int d = i >> 7, j1 = i & 127;
        smh[H_QS + j1 * 40 + d] = __float2half_rn(W1[i]);     // i = d*128 + j1
        int j2 = i >> 5, c = i & 31;
        smh[H_KS + c * 136 + j2] = __float2half_rn(W2[i]);    // i = j2*32 + c
    }
    __syncthreads();

    // ================= Wo: [128,32] @ [32,32] -> OS (f32); warp = 16 rows =================
    {
        const int rb = w * 16;
        u32 A[2][4];
        LDA(A[0], smh + H_XN, rb, 0,  40);
        LDA(A[1], smh + H_XN, rb, 16, 40);
        float c[4][4];
#pragma unroll
        for (int b = 0; b < 4; b++)
#pragma unroll
            for (int q = 0; q < 4; q++) c[b][q] = 0.f;
#pragma unroll
        for (int kt = 0; kt < 2; kt++) {
#pragma unroll
            for (int n2 = 0; n2 < 2; n2++) {
                u32 Bv[4];
                LDB4(Bv, smh + H_WB, n2 * 16, kt * 16, 40);
                mma16a(c[2*n2],     A[kt], Bv[0], Bv[1]);
                mma16a(c[2*n2 + 1], A[kt], Bv[2], Bv[3]);
            }
        }
#pragma unroll
        for (int nt = 0; nt < 4; nt++) {
            *reinterpret_cast<float2*>(&smf[F_OS + (rb + lr)     * 36 + nt*8 + 2*lc]) =
                make_float2(c[nt][0], c[nt][1]);
            *reinterpret_cast<float2*>(&smf[F_OS + (rb + lr + 8) * 36 + nt*8 + 2*lc]) =
                make_float2(c[nt][2], c[nt][3]);
        }
    }
    __syncthreads();

    // ---- residual + LN2 (scalar, rows 0..127); write ZN half into XN ----
    float z[32];
    if (t < TT) {
        const float* os = smf + F_OS + t * 36;
#pragma unroll
        for (int c = 0; c < 32; c++) z[c] = xn[c] + os[c] + smf[F_BO + c];
        ln32(z, smf + F_G2, smf + F_BE2);
        u32* zr = reinterpret_cast<u32*>(smh + H_XN + t * 40);
#pragma unroll
        for (int p = 0; p < 16; p++) zr[p] = h2(z[2*p], z[2*p+1]);
    }
    __syncthreads();

    // ================= FFN: relu(ZN@W1+b1)@W2 fused via per-warp chunk; warp = 16 rows =================
    {
        __half* ck = smh + H_WB + w * 384;   // [16][24]
        const int rb = w * 16;
        u32 A[2][4];
        LDA(A[0], smh + H_XN, rb, 0,  40);
        LDA(A[1], smh + H_XN, rb, 16, 40);
        float cf[4][4];
#pragma unroll
        for (int b = 0; b < 4; b++)
#pragma unroll
            for (int q = 0; q < 4; q++) cf[b][q] = 0.f;
#pragma unroll
        for (int g = 0; g < 8; g++) {
            float hv[2][4];
#pragma unroll
            for (int b = 0; b < 2; b++)
#pragma unroll
                for (int q = 0; q < 4; q++) hv[b][q] = 0.f;
#pragma unroll
            for (int kt = 0; kt < 2; kt++) {
                u32 Bv[4];
                LDB4(Bv, smh + H_QS, g * 16, kt * 16, 40);
                mma16a(hv[0], A[kt], Bv[0], Bv[1]);
                mma16a(hv[1], A[kt], Bv[2], Bv[3]);
            }
#pragma unroll
            for (int ntl = 0; ntl < 2; ntl++) {
                const int nt = 2 * g + ntl;
                const float bj0 = smf[F_B1 + nt*8 + 2*lc];
                const float bj1 = smf[F_B1 + nt*8 + 2*lc + 1];
                float p0 = fmaxf(hv[ntl][0] + bj0, 0.f);
                float p1 = fmaxf(hv[ntl][1] + bj1, 0.f);
                float p2 = fmaxf(hv[ntl][2] + bj0, 0.f);
                float p3 = fmaxf(hv[ntl][3] + bj1, 0.f);
                *reinterpret_cast<u32*>(&ck[lr * 24       + ntl*8 + 2*lc]) = h2(p0, p1);
                *reinterpret_cast<u32*>(&ck[(lr + 8) * 24 + ntl*8 + 2*lc]) = h2(p2, p3);
            }
            __syncwarp();
            u32 PA[4];
            LDA(PA, ck, 0, 0, 24);
#pragma unroll
            for (int n2 = 0; n2 < 2; n2++) {
                u32 Bv[4];
                LDB4(Bv, smh + H_KS, n2 * 16, g * 16, 136);
                mma16a(cf[2*n2],     PA, Bv[0], Bv[1]);
                mma16a(cf[2*n2 + 1], PA, Bv[2], Bv[3]);
            }
            __syncwarp();
        }
#pragma unroll
        for (int nt2 = 0; nt2 < 4; nt2++) {
            *reinterpret_cast<float2*>(&smf[F_OS + (rb + lr)     * 36 + nt2*8 + 2*lc]) =
                make_float2(cf[nt2][0], cf[nt2][1]);
            *reinterpret_cast<float2*>(&smf[F_OS + (rb + lr + 8) * 36 + nt2*8 + 2*lc]) =
                make_float2(cf[nt2][2], cf[nt2][3]);
        }
    }
    __syncthreads();

    // ---- final residual + store (rows 0..127) ----
    if (t < TT) {
        const float* r = smf + F_OS + t * 36;
        float4* o4 = reinterpret_cast<float4*>(out + rowbase);
#pragma unroll
        for (int c4 = 0; c4 < 8; c4++)
            o4[c4] = make_float4(z[4*c4+0] + r[4*c4+0] + smf[F_B2 + 4*c4+0],
                                 z[4*c4+1] + r[4*c4+1] + smf[F_B2 + 4*c4+1],
                                 z[4*c4+2] + r[4*c4+2] + smf[F_B2 + 4*c4+2],
                                 z[4*c4+3] + r[4*c4+3] + smf[F_B2 + 4*c4+3]);
    }
}

extern "C" void kernel_launch(void* const* d_in, const int* in_sizes, int n_in,
                              void* d_out, int out_size) {
    const float* x   = (const float*)d_in[0];
    const float* Wq  = (const float*)d_in[1];
    const float* Wk  = (const float*)d_in[2];
    const float* Wv  = (const float*)d_in[3];
    const float* Wo  = (const float*)d_in[4];
    const float* bo  = (const float*)d_in[5];
    const float* W1  = (const float*)d_in[6];
    const float* b1  = (const float*)d_in[7];
    const float* W2  = (const float*)d_in[8];
    const float* b2  = (const float*)d_in[9];
    const float* g1  = (const float*)d_in[10];
    const float* be1 = (const float*)d_in[11];
    const float* g2  = (const float*)d_in[12];
    const float* be2 = (const float*)d_in[13];

    int B = in_sizes[0] / (TT * DMM);
    cudaFuncSetAttribute(block_fused, cudaFuncAttributeMaxDynamicSharedMemorySize, SMEM_BYTES);
    block_fused<<<B, 256, SMEM_BYTES>>>(x, Wq, Wk, Wv, Wo, bo, W1, b1, W2, b2,
                                        g1, be1, g2, be2, (float*)d_out);
}

// round 12
// speedup vs baseline: 2.7704x; 1.0604x over previous
#include <cuda_runtime.h>
#include <cuda_fp16.h>
#include <math.h>
#include <stdint.h>

#define TT 128
#define DMM 32

typedef uint32_t u32;

// ---- f32 region (float offsets) ----
#define F_BO   0
#define F_B2   32
#define F_G1   64
#define F_BE1  96
#define F_G2   128
#define F_BE2  160
#define F_B1   192          // 128 floats
#define F_OS   320          // [128][36] f32 (Wo out, then FFN out)
#define F_END  (320 + 128*36)
// ---- half region (half offsets), starts at byte 4*F_END ----
#define H_XN   0            // [128][40]  xn -> at -> zn
#define H_QS   5120         // [128][40]  Q  -> W1t[128][40]
#define H_KS   10240        // [128][40]  K  -> W2t[32][136]
#define H_VT   15360        // [32][136]  V^T (dv-major, keys contiguous)
#define H_WB   19712        // [96][40] WqkvT -> WoT[32][40]
#define H_END  (19712 + 3840)
#define SMEM_BYTES (4*F_END + 2*H_END)   // 66816

__device__ __forceinline__ u32 sadd(const __half* p) {
    return static_cast<u32>(__cvta_generic_to_shared(p));
}
__device__ __forceinline__ void ldsm4(u32 (&r)[4], u32 a) {
    asm volatile("ldmatrix.sync.aligned.m8n8.x4.shared.b16 {%0,%1,%2,%3}, [%4];"
                 : "=r"(r[0]), "=r"(r[1]), "=r"(r[2]), "=r"(r[3]) : "r"(a));
}
// D += A(16x16,row) * B(16x8,col), f16 in, f32 accum
__device__ __forceinline__ void mma16a(float (&d)[4], const u32 (&a)[4], u32 b0, u32 b1) {
    asm("mma.sync.aligned.m16n8k16.row.col.f32.f16.f16.f32 "
        "{%0,%1,%2,%3}, {%4,%5,%6,%7}, {%8,%9}, {%0,%1,%2,%3};"
        : "+f"(d[0]), "+f"(d[1]), "+f"(d[2]), "+f"(d[3])
        : "r"(a[0]), "r"(a[1]), "r"(a[2]), "r"(a[3]), "r"(b0), "r"(b1));
}
__device__ __forceinline__ u32 h2(float lo, float hi) {
    __half2 v = __floats2half2_rn(lo, hi);
    return *reinterpret_cast<u32*>(&v);
}

// A m16k16 fragment (rows rb.., cols kb0.., stride S halves)
#define LDA(Areg, bp, rb, kb0, S) \
    ldsm4(Areg, sadd((bp) + ((rb) + (lam & 15)) * (S) + (kb0) + (lam >> 4) * 8))
// B: two n8-tiles (nb, nb+8) x k16 at kb0 -> {b0,b1}tile0, {b0,b1}tile1
#define LDB4(Breg, bp, nb, kb0, S) \
    ldsm4(Breg, sadd((bp) + ((nb) + ((lam >> 4) & 1) * 8 + (lam & 7)) * (S) + (kb0) + ((lam >> 3) & 1) * 8))

__device__ __forceinline__ void ln32(float (&v)[32], const float* g, const float* be) {
    float mu = 0.0f;
#pragma unroll
    for (int i = 0; i < 32; i++) mu += v[i];
    mu *= (1.0f / 32.0f);
    float var = 0.0f;
#pragma unroll
    for (int i = 0; i < 32; i++) { float d = v[i] - mu; var = fmaf(d, d, var); }
    var *= (1.0f / 32.0f);
    float rstd = rsqrtf(var + 1e-5f);
#pragma unroll
    for (int i = 0; i < 32; i++) v[i] = fmaf((v[i] - mu) * rstd, g[i], be[i]);
}

__global__ void __launch_bounds__(256, 3) block_fused(
    const float* __restrict__ x,
    const float* __restrict__ Wq, const float* __restrict__ Wk, const float* __restrict__ Wv,
    const float* __restrict__ Wo, const float* __restrict__ bo,
    const float* __restrict__ W1, const float* __restrict__ b1,
    const float* __restrict__ W2, const float* __restrict__ b2,
    const float* __restrict__ g1, const float* __restrict__ be1,
    const float* __restrict__ g2, const float* __restrict__ be2,
    float* __restrict__ out)
{
    extern __shared__ char smraw[];
    float* smf = reinterpret_cast<float*>(smraw);
    __half* smh = reinterpret_cast<__half*>(smraw + 4 * F_END);

    const int tid = threadIdx.x;
    const int t = tid;                       // token row for scalar phases (tid < 128)
    const int lam = tid & 31, w = tid >> 5;  // 8 warps
    const int lr = lam >> 2, lc = lam & 3;
    const size_t rowbase = ((size_t)blockIdx.x * TT + t) * DMM;

    // early x row load (rows 0..127 only)
    float4 xv4[8];
    if (t < TT) {
        const float4* xrow = reinterpret_cast<const float4*>(x + rowbase);
#pragma unroll
        for (int i = 0; i < 8; i++) xv4[i] = xrow[i];
    }

    // ---- stage Wqkv^T [96 n][40 k=d]; n: 0-31 Q, 32-63 K, 64-95 V; within: h*16+kk ----
    for (int i = tid; i < 3072; i += 256) {
        int n = i >> 5, d = i & 31;
        int sel = n >> 5, j = n & 31, hj = j >> 4, kk = j & 15;
        const float* Wsrc = (sel == 0) ? Wq : (sel == 1) ? Wk : Wv;
        smh[H_WB + n * 40 + d] = __float2half_rn(Wsrc[hj * 512 + d * 16 + kk]);
    }
    if (tid < 32) {
        smf[F_BO  + tid] = bo[tid];  smf[F_B2  + tid] = b2[tid];
        smf[F_G1  + tid] = g1[tid];  smf[F_BE1 + tid] = be1[tid];
        smf[F_G2  + tid] = g2[tid];  smf[F_BE2 + tid] = be2[tid];
    }
    if (tid < 128) smf[F_B1 + tid] = b1[tid];
    __syncthreads();

    // ---- LN1 (scalar, rows 0..127); xn kept in regs; write half row to XN ----
    float xn[32];
    if (t < TT) {
#pragma unroll
        for (int i = 0; i < 8; i++) {
            xn[4*i+0] = xv4[i].x; xn[4*i+1] = xv4[i].y;
            xn[4*i+2] = xv4[i].z; xn[4*i+3] = xv4[i].w;
        }
        ln32(xn, smf + F_G1, smf + F_BE1);
        u32* xr = reinterpret_cast<u32*>(smh + H_XN + t * 40);
#pragma unroll
        for (int p = 0; p < 16; p++) xr[p] = h2(xn[2*p], xn[2*p+1]);
    }
    __syncthreads();

    // ================= QKV: [128,32] @ [32,96]; warp owns 16 rows =================
    {
        const int rb = w * 16;
        u32 A[2][4];
        LDA(A[0], smh + H_XN, rb, 0,  40);
        LDA(A[1], smh + H_XN, rb, 16, 40);
#pragma unroll
        for (int np = 0; np < 6; np++) {
            float c[2][4];
#pragma unroll
            for (int b = 0; b < 2; b++)
#pragma unroll
                for (int q = 0; q < 4; q++) c[b][q] = 0.f;
#pragma unroll
            for (int kt = 0; kt < 2; kt++) {
                u32 Bv[4];
                LDB4(Bv, smh + H_WB, np * 16, kt * 16, 40);
                mma16a(c[0], A[kt], Bv[0], Bv[1]);
                mma16a(c[1], A[kt], Bv[2], Bv[3]);
            }
#pragma unroll
            for (int ntl = 0; ntl < 2; ntl++) {
                const int nt = 2 * np + ntl;
                const int sel = nt >> 2, colb = (nt & 3) * 8 + 2 * lc;
                if (sel < 2) {
                    __half* dst = smh + (sel == 0 ? H_QS : H_KS);
                    *reinterpret_cast<u32*>(&dst[(rb + lr)     * 40 + colb]) = h2(c[ntl][0], c[ntl][1]);
                    *reinterpret_cast<u32*>(&dst[(rb + lr + 8) * 40 + colb]) = h2(c[ntl][2], c[ntl][3]);
                } else {  // V transposed: Vt[dv][token]
                    smh[H_VT + colb       * 136 + rb + lr]     = __float2half_rn(c[ntl][0]);
                    smh[H_VT + (colb + 1) * 136 + rb + lr]     = __float2half_rn(c[ntl][1]);
                    smh[H_VT + colb       * 136 + rb + lr + 8] = __float2half_rn(c[ntl][2]);
                    smh[H_VT + (colb + 1) * 136 + rb + lr + 8] = __float2half_rn(c[ntl][3]);
                }
            }
        }
    }
    __syncthreads();

    // ================= causal attention: warp = (head, balanced qt pair {ws, 7-ws}) =================
    // S fragments are masked+exp'd and repacked to A fragments IN REGISTERS (FA2 trick):
    // C(m16n8): c0,c1=row lr cols 2lc,2lc+1; c2,c3=row lr+8 -> a = h2 pairs, two n8 tiles per k16.
    {
        const int h = w & 1, ws = w >> 1;
#pragma unroll
        for (int qi = 0; qi < 2; qi++) {
            const int qt = qi ? (7 - ws) : ws;    // depths: 5/5/4/4 key-blocks per warp
            const int nkb = (qt >> 1) + 1;
            u32 QA[4];
            LDA(QA, smh + H_QS, qt * 16, h * 16, 40);
            float o[2][4];
#pragma unroll
            for (int b = 0; b < 2; b++)
#pragma unroll
                for (int q = 0; q < 4; q++) o[b][q] = 0.f;
            float l_lo = 0.f, l_hi = 0.f;
            const int q_lo = qt * 16 + lr, q_hi = q_lo + 8;
            for (int kb = 0; kb < nkb; kb++) {
                float s[4][4];
#pragma unroll
                for (int n2 = 0; n2 < 2; n2++) {
                    u32 Bv[4];
                    LDB4(Bv, smh + H_KS, kb * 32 + n2 * 16, h * 16, 40);
                    s[2*n2][0] = s[2*n2][1] = s[2*n2][2] = s[2*n2][3] = 0.f;
                    s[2*n2+1][0] = s[2*n2+1][1] = s[2*n2+1][2] = s[2*n2+1][3] = 0.f;
                    mma16a(s[2*n2],     QA, Bv[0], Bv[1]);
                    mma16a(s[2*n2 + 1], QA, Bv[2], Bv[3]);
                }
                u32 PA[2][4];
#pragma unroll
                for (int ntk = 0; ntk < 4; ntk++) {
                    const int key0 = kb * 32 + ntk * 8 + 2 * lc;
                    float p0 = (key0     <= q_lo) ? __expf(s[ntk][0]) : 0.f;
                    float p1 = (key0 + 1 <= q_lo) ? __expf(s[ntk][1]) : 0.f;
                    float p2 = (key0     <= q_hi) ? __expf(s[ntk][2]) : 0.f;
                    float p3 = (key0 + 1 <= q_hi) ? __expf(s[ntk][3]) : 0.f;
                    l_lo += p0 + p1;  l_hi += p2 + p3;
                    PA[ntk >> 1][(ntk & 1) * 2]     = h2(p0, p1);
                    PA[ntk >> 1][(ntk & 1) * 2 + 1] = h2(p2, p3);
                }
#pragma unroll
                for (int ks = 0; ks < 2; ks++) {
                    u32 Vv[4];
                    LDB4(Vv, smh + H_VT, h * 16, kb * 32 + ks * 16, 136);
                    mma16a(o[0], PA[ks], Vv[0], Vv[1]);
                    mma16a(o[1], PA[ks], Vv[2], Vv[3]);
                }
            }
            l_lo += __shfl_xor_sync(0xffffffffu, l_lo, 1);
            l_lo += __shfl_xor_sync(0xffffffffu, l_lo, 2);
            l_hi += __shfl_xor_sync(0xffffffffu, l_hi, 1);
            l_hi += __shfl_xor_sync(0xffffffffu, l_hi, 2);
            const float il = __fdividef(1.f, l_lo), ih = __fdividef(1.f, l_hi);
            const int qr = qt * 16;
#pragma unroll
            for (int nv = 0; nv < 2; nv++) {
                *reinterpret_cast<u32*>(&smh[H_XN + (qr + lr)     * 40 + h*16 + nv*8 + 2*lc]) =
                    h2(o[nv][0] * il, o[nv][1] * il);
                *reinterpret_cast<u32*>(&smh[H_XN + (qr + lr + 8) * 40 + h*16 + nv*8 + 2*lc]) =
                    h2(o[nv][2] * ih, o[nv][3] * ih);
            }
        }
    }
    __syncthreads();

    // ---- stage WoT [32 c][40 j], W1t [128 j][40 d], W2t [32 c][136 j] ----
    for (int i = tid; i < 1024; i += 256) {
        int j = i >> 5, c = i & 31;
        smh[H_WB + c * 40 + j] = __float2half_rn(Wo[i]);      // i = j*32 + c
    }
    for (int i = tid; i < 4096; i += 256) {
        int d = i >> 7, j1 = i & 127;
        smh[H_QS + j1 * 40 + d] = __float2half_rn(W1[i]);     // i = d*128 + j1
        int j2 = i >> 5, c = i & 31;
        smh[H_KS + c * 136 + j2] = __float2half_rn(W2[i]);    // i = j2*32 + c
    }
    __syncthreads();

    // ================= Wo: [128,32] @ [32,32] -> OS (f32); warp = 16 rows =================
    {
        const int rb = w * 16;
        u32 A[2][4];
        LDA(A[0], smh + H_XN, rb, 0,  40);
        LDA(A[1], smh + H_XN, rb, 16, 40);
        float c[4][4];
#pragma unroll
        for (int b = 0; b < 4; b++)
#pragma unroll
            for (int q = 0; q < 4; q++) c[b][q] = 0.f;
#pragma unroll
        for (int kt = 0; kt < 2; kt++) {
#pragma unroll
            for (int n2 = 0; n2 < 2; n2++) {
                u32 Bv[4];
                LDB4(Bv, smh + H_WB, n2 * 16, kt * 16, 40);
                mma16a(c[2*n2],     A[kt], Bv[0], Bv[1]);
                mma16a(c[2*n2 + 1], A[kt], Bv[2], Bv[3]);
            }
        }
#pragma unroll
        for (int nt = 0; nt < 4; nt++) {
            *reinterpret_cast<float2*>(&smf[F_OS + (rb + lr)     * 36 + nt*8 + 2*lc]) =
                make_float2(c[nt][0], c[nt][1]);
            *reinterpret_cast<float2*>(&smf[F_OS + (rb + lr + 8) * 36 + nt*8 + 2*lc]) =
                make_float2(c[nt][2], c[nt][3]);
        }
    }
    __syncthreads();

    // ---- residual + LN2 (scalar, rows 0..127); write ZN half into XN ----
    float z[32];
    if (t < TT) {
        const float* os = smf + F_OS + t * 36;
#pragma unroll
        for (int c = 0; c < 32; c++) z[c] = xn[c] + os[c] + smf[F_BO + c];
        ln32(z, smf + F_G2, smf + F_BE2);
        u32* zr = reinterpret_cast<u32*>(smh + H_XN + t * 40);
#pragma unroll
        for (int p = 0; p < 16; p++) zr[p] = h2(z[2*p], z[2*p+1]);
    }
    __syncthreads();

    // ================= FFN: relu(ZN@W1+b1)@W2, H repacked in registers =================
    {
        const int rb = w * 16;
        u32 A[2][4];
        LDA(A[0], smh + H_XN, rb, 0,  40);
        LDA(A[1], smh + H_XN, rb, 16, 40);
        float cf[4][4];
#pragma unroll
        for (int b = 0; b < 4; b++)
#pragma unroll
            for (int q = 0; q < 4; q++) cf[b][q] = 0.f;
#pragma unroll
        for (int g = 0; g < 8; g++) {
            float hv[2][4];
#pragma unroll
            for (int b = 0; b < 2; b++)
#pragma unroll
                for (int q = 0; q < 4; q++) hv[b][q] = 0.f;
#pragma unroll
            for (int kt = 0; kt < 2; kt++) {
                u32 Bv[4];
                LDB4(Bv, smh + H_QS, g * 16, kt * 16, 40);
                mma16a(hv[0], A[kt], Bv[0], Bv[1]);
                mma16a(hv[1], A[kt], Bv[2], Bv[3]);
            }
            u32 PA[4];
#pragma unroll
            for (int ntl = 0; ntl < 2; ntl++) {
                const int nt = 2 * g + ntl;
                const float bj0 = smf[F_B1 + nt*8 + 2*lc];
                const float bj1 = smf[F_B1 + nt*8 + 2*lc + 1];
                float p0 = fmaxf(hv[ntl][0] + bj0, 0.f);
                float p1 = fmaxf(hv[ntl][1] + bj1, 0.f);
                float p2 = fmaxf(hv[ntl][2] + bj0, 0.f);
                float p3 = fmaxf(hv[ntl][3] + bj1, 0.f);
                PA[ntl * 2]     = h2(p0, p1);
                PA[ntl * 2 + 1] = h2(p2, p3);
            }
#pragma unroll
            for (int n2 = 0; n2 < 2; n2++) {
                u32 Bv[4];
                LDB4(Bv, smh + H_KS, n2 * 16, g * 16, 136);
                mma16a(cf[2*n2],     PA, Bv[0], Bv[1]);
                mma16a(cf[2*n2 + 1], PA, Bv[2], Bv[3]);
            }
        }
#pragma unroll
        for (int nt2 = 0; nt2 < 4; nt2++) {
            *reinterpret_cast<float2*>(&smf[F_OS + (rb + lr)     * 36 + nt2*8 + 2*lc]) =
                make_float2(cf[nt2][0], cf[nt2][1]);
            *reinterpret_cast<float2*>(&smf[F_OS + (rb + lr + 8) * 36 + nt2*8 + 2*lc]) =
                make_float2(cf[nt2][2], cf[nt2][3]);
        }
    }
    __syncthreads();

    // ---- final residual + store (rows 0..127) ----
    if (t < TT) {
        const float* r = smf + F_OS + t * 36;
        float4* o4 = reinterpret_cast<float4*>(out + rowbase);
#pragma unroll
        for (int c4 = 0; c4 < 8; c4++)
            o4[c4] = make_float4(z[4*c4+0] + r[4*c4+0] + smf[F_B2 + 4*c4+0],
                                 z[4*c4+1] + r[4*c4+1] + smf[F_B2 + 4*c4+1],
                                 z[4*c4+2] + r[4*c4+2] + smf[F_B2 + 4*c4+2],
                                 z[4*c4+3] + r[4*c4+3] + smf[F_B2 + 4*c4+3]);
    }
}

extern "C" void kernel_launch(void* const* d_in, const int* in_sizes, int n_in,
                              void* d_out, int out_size) {
    const float* x   = (const float*)d_in[0];
    const float* Wq  = (const float*)d_in[1];
    const float* Wk  = (const float*)d_in[2];
    const float* Wv  = (const float*)d_in[3];
    const float* Wo  = (const float*)d_in[4];
    const float* bo  = (const float*)d_in[5];
    const float* W1  = (const float*)d_in[6];
    const float* b1  = (const float*)d_in[7];
    const float* W2  = (const float*)d_in[8];
    const float* b2  = (const float*)d_in[9];
    const float* g1  = (const float*)d_in[10];
    const float* be1 = (const float*)d_in[11];
    const float* g2  = (const float*)d_in[12];
    const float* be2 = (const float*)d_in[13];

    int B = in_sizes[0] / (TT * DMM);
    cudaFuncSetAttribute(block_fused, cudaFuncAttributeMaxDynamicSharedMemorySize, SMEM_BYTES);
    block_fused<<<B, 256, SMEM_BYTES>>>(x, Wq, Wk, Wv, Wo, bo, W1, b1, W2, b2,
                                        g1, be1, g2, be2, (float*)d_out);
}

// round 15
// speedup vs baseline: 2.8311x; 1.0219x over previous
#include <cuda_runtime.h>
#include <cuda_fp16.h>
#include <math.h>
#include <stdint.h>

#define TT 128
#define DMM 32

typedef uint32_t u32;

// ---- f32 region (float offsets) ----
#define F_BO   0
#define F_B2   32
#define F_G1   64
#define F_BE1  96
#define F_G2   128
#define F_BE2  160
#define F_B1   192          // 128 floats
#define F_OS   320          // [128][36] f32 (Wo out, then FFN out)
#define F_END  (320 + 128*36)
// ---- half region (half offsets), starts at byte 4*F_END ----
#define H_XN   0            // [128][40]  xn -> at -> zn
#define H_QS   5120         // [128][40]  Q  -> W1t[128][40]
#define H_KS   10240        // [128][40]  K  -> W2t[32][136]
#define H_VT   15360        // [32][136]  V^T (dv-major, keys contiguous)
#define H_WB   19712        // [96][40] WqkvT -> WoT[32][40]
#define H_END  23552
#define SMEM_BYTES (4*F_END + 2*H_END)   // 66816

__device__ __forceinline__ u32 sadd(const __half* p) {
    return static_cast<u32>(__cvta_generic_to_shared(p));
}
__device__ __forceinline__ void ldsm4(u32 (&r)[4], u32 a) {
    asm volatile("ldmatrix.sync.aligned.m8n8.x4.shared.b16 {%0,%1,%2,%3}, [%4];"
                 : "=r"(r[0]), "=r"(r[1]), "=r"(r[2]), "=r"(r[3]) : "r"(a));
}
// D += A(16x16,row) * B(16x8,col), f16 in, f32 accum
__device__ __forceinline__ void mma16a(float (&d)[4], const u32 (&a)[4], u32 b0, u32 b1) {
    asm("mma.sync.aligned.m16n8k16.row.col.f32.f16.f16.f32 "
        "{%0,%1,%2,%3}, {%4,%5,%6,%7}, {%8,%9}, {%0,%1,%2,%3};"
        : "+f"(d[0]), "+f"(d[1]), "+f"(d[2]), "+f"(d[3])
        : "r"(a[0]), "r"(a[1]), "r"(a[2]), "r"(a[3]), "r"(b0), "r"(b1));
}
__device__ __forceinline__ u32 h2(float lo, float hi) {
    __half2 v = __floats2half2_rn(lo, hi);
    return *reinterpret_cast<u32*>(&v);
}

// A m16k16 fragment (rows rb.., cols kb0.., stride S halves)
#define LDA(Areg, bp, rb, kb0, S) \
    ldsm4(Areg, sadd((bp) + ((rb) + (lam & 15)) * (S) + (kb0) + (lam >> 4) * 8))
// B (k-major source): two n8-tiles (nb, nb+8) x k16 at kb0
#define LDB4(Breg, bp, nb, kb0, S) \
    ldsm4(Breg, sadd((bp) + ((nb) + ((lam >> 4) & 1) * 8 + (lam & 7)) * (S) + (kb0) + ((lam >> 3) & 1) * 8))

__device__ __forceinline__ void ln32(float (&v)[32], const float* g, const float* be) {
    float mu = 0.0f;
#pragma unroll
    for (int i = 0; i < 32; i++) mu += v[i];
    mu *= (1.0f / 32.0f);
    float var = 0.0f;
#pragma unroll
    for (int i = 0; i < 32; i++) { float d = v[i] - mu; var = fmaf(d, d, var); }
    var *= (1.0f / 32.0f);
    float rstd = rsqrtf(var + 1e-5f);
#pragma unroll
    for (int i = 0; i < 32; i++) v[i] = fmaf((v[i] - mu) * rstd, g[i], be[i]);
}

__global__ void __launch_bounds__(256, 3) block_fused(
    const float* __restrict__ x,
    const float* __restrict__ Wq, const float* __restrict__ Wk, const float* __restrict__ Wv,
    const float* __restrict__ Wo, const float* __restrict__ bo,
    const float* __restrict__ W1, const float* __restrict__ b1,
    const float* __restrict__ W2, const float* __restrict__ b2,
    const float* __restrict__ g1, const float* __restrict__ be1,
    const float* __restrict__ g2, const float* __restrict__ be2,
    float* __restrict__ out)
{
    extern __shared__ char smraw[];
    float* smf = reinterpret_cast<float*>(smraw);
    __half* smh = reinterpret_cast<__half*>(smraw + 4 * F_END);

    const int tid = threadIdx.x;
    const int t = tid;                       // token row for scalar phases (tid < 128)
    const int lam = tid & 31, w = tid >> 5;  // 8 warps
    const int lr = lam >> 2, lc = lam & 3;
    const size_t rowbase = ((size_t)blockIdx.x * TT + t) * DMM;

    // early x row load (rows 0..127 only)
    float4 xv4[8];
    if (t < TT) {
        const float4* xrow = reinterpret_cast<const float4*>(x + rowbase);
#pragma unroll
        for (int i = 0; i < 8; i++) xv4[i] = xrow[i];
    }

    // ---- stage WqkvT [96 n][40 k=d]; n: 0-31 Q, 32-63 K, 64-95 V; within: h*16+kk ----
    for (int i = tid; i < 3072; i += 256) {
        int n = i >> 5, d = i & 31;
        int sel = n >> 5, j = n & 31, hj = j >> 4, kk = j & 15;
        const float* Wsrc = (sel == 0) ? Wq : (sel == 1) ? Wk : Wv;
        smh[H_WB + n * 40 + d] = __float2half_rn(Wsrc[hj * 512 + d * 16 + kk]);
    }
    if (tid < 32) {
        smf[F_BO  + tid] = bo[tid];  smf[F_B2  + tid] = b2[tid];
        smf[F_G1  + tid] = g1[tid];  smf[F_BE1 + tid] = be1[tid];
        smf[F_G2  + tid] = g2[tid];  smf[F_BE2 + tid] = be2[tid];
    }
    if (tid < 128) smf[F_B1 + tid] = b1[tid];
    __syncthreads();

    // ---- LN1 (scalar, rows 0..127); xn kept in regs; write half row to XN ----
    float xn[32];
    if (t < TT) {
#pragma unroll
        for (int i = 0; i < 8; i++) {
            xn[4*i+0] = xv4[i].x; xn[4*i+1] = xv4[i].y;
            xn[4*i+2] = xv4[i].z; xn[4*i+3] = xv4[i].w;
        }
        ln32(xn, smf + F_G1, smf + F_BE1);
        u32* xr = reinterpret_cast<u32*>(smh + H_XN + t * 40);
#pragma unroll
        for (int p = 0; p < 16; p++) xr[p] = h2(xn[2*p], xn[2*p+1]);
    }
    __syncthreads();

    // ================= QKV: [128,32] @ [32,96]; warp owns 16 rows =================
    {
        const int rb = w * 16;
        u32 A[2][4];
        LDA(A[0], smh + H_XN, rb, 0,  40);
        LDA(A[1], smh + H_XN, rb, 16, 40);
#pragma unroll
        for (int np = 0; np < 6; np++) {
            float c[2][4];
#pragma unroll
            for (int b = 0; b < 2; b++)
#pragma unroll
                for (int q = 0; q < 4; q++) c[b][q] = 0.f;
#pragma unroll
            for (int kt = 0; kt < 2; kt++) {
                u32 Bv[4];
                LDB4(Bv, smh + H_WB, np * 16, kt * 16, 40);
                mma16a(c[0], A[kt], Bv[0], Bv[1]);
                mma16a(c[1], A[kt], Bv[2], Bv[3]);
            }
#pragma unroll
            for (int ntl = 0; ntl < 2; ntl++) {
                const int nt = 2 * np + ntl;
                const int sel = nt >> 2, colb = (nt & 3) * 8 + 2 * lc;
                if (sel < 2) {
                    __half* dst = smh + (sel == 0 ? H_QS : H_KS);
                    *reinterpret_cast<u32*>(&dst[(rb + lr)     * 40 + colb]) = h2(c[ntl][0], c[ntl][1]);
                    *reinterpret_cast<u32*>(&dst[(rb + lr + 8) * 40 + colb]) = h2(c[ntl][2], c[ntl][3]);
                } else {  // V transposed: Vt[dv][token]
                    smh[H_VT + colb       * 136 + rb + lr]     = __float2half_rn(c[ntl][0]);
                    smh[H_VT + (colb + 1) * 136 + rb + lr]     = __float2half_rn(c[ntl][1]);
                    smh[H_VT + colb       * 136 + rb + lr + 8] = __float2half_rn(c[ntl][2]);
                    smh[H_VT + (colb + 1) * 136 + rb + lr + 8] = __float2half_rn(c[ntl][3]);
                }
            }
        }
    }
    __syncthreads();

    // ================= causal attention: warp = (head, balanced qt pair {ws, 7-ws}) =================
    // P repacked in registers (FA2 trick). kb loop split: full blocks (no mask) + diagonal (masked).
    {
        const int h = w & 1, ws = w >> 1;
#pragma unroll
        for (int qi = 0; qi < 2; qi++) {
            const int qt = qi ? (7 - ws) : ws;    // depths: 5/5/4/4 key-blocks per warp
            const int nkb = (qt >> 1) + 1;
            u32 QA[4];
            LDA(QA, smh + H_QS, qt * 16, h * 16, 40);
            float o[2][4];
#pragma unroll
            for (int b = 0; b < 2; b++)
#pragma unroll
                for (int q = 0; q < 4; q++) o[b][q] = 0.f;
            float l_lo = 0.f, l_hi = 0.f;
            const int q_lo = qt * 16 + lr, q_hi = q_lo + 8;
            // ---- full (unmasked) key-blocks: all keys < qt*16 <= q_lo ----
            for (int kb = 0; kb < nkb - 1; kb++) {
                float s[4][4];
#pragma unroll
                for (int n2 = 0; n2 < 2; n2++) {
                    u32 Bv[4];
                    LDB4(Bv, smh + H_KS, kb * 32 + n2 * 16, h * 16, 40);
                    s[2*n2][0] = s[2*n2][1] = s[2*n2][2] = s[2*n2][3] = 0.f;
                    s[2*n2+1][0] = s[2*n2+1][1] = s[2*n2+1][2] = s[2*n2+1][3] = 0.f;
                    mma16a(s[2*n2],     QA, Bv[0], Bv[1]);
                    mma16a(s[2*n2 + 1], QA, Bv[2], Bv[3]);
                }
                u32 PA[2][4];
#pragma unroll
                for (int ntk = 0; ntk < 4; ntk++) {
                    float p0 = __expf(s[ntk][0]);
                    float p1 = __expf(s[ntk][1]);
                    float p2 = __expf(s[ntk][2]);
                    float p3 = __expf(s[ntk][3]);
                    l_lo += p0 + p1;  l_hi += p2 + p3;
                    PA[ntk >> 1][(ntk & 1) * 2]     = h2(p0, p1);
                    PA[ntk >> 1][(ntk & 1) * 2 + 1] = h2(p2, p3);
                }
#pragma unroll
                for (int ks = 0; ks < 2; ks++) {
                    u32 Vv[4];
                    LDB4(Vv, smh + H_VT, h * 16, kb * 32 + ks * 16, 136);
                    mma16a(o[0], PA[ks], Vv[0], Vv[1]);
                    mma16a(o[1], PA[ks], Vv[2], Vv[3]);
                }
            }
            // ---- diagonal (masked) key-block ----
            {
                const int kb = nkb - 1;
                float s[4][4];
#pragma unroll
                for (int n2 = 0; n2 < 2; n2++) {
                    u32 Bv[4];
                    LDB4(Bv, smh + H_KS, kb * 32 + n2 * 16, h * 16, 40);
                    s[2*n2][0] = s[2*n2][1] = s[2*n2][2] = s[2*n2][3] = 0.f;
                    s[2*n2+1][0] = s[2*n2+1][1] = s[2*n2+1][2] = s[2*n2+1][3] = 0.f;
                    mma16a(s[2*n2],     QA, Bv[0], Bv[1]);
                    mma16a(s[2*n2 + 1], QA, Bv[2], Bv[3]);
                }
                u32 PA[2][4];
#pragma unroll
                for (int ntk = 0; ntk < 4; ntk++) {
                    const int key0 = kb * 32 + ntk * 8 + 2 * lc;
                    float p0 = (key0     <= q_lo) ? __expf(s[ntk][0]) : 0.f;
                    float p1 = (key0 + 1 <= q_lo) ? __expf(s[ntk][1]) : 0.f;
                    float p2 = (key0     <= q_hi) ? __expf(s[ntk][2]) : 0.f;
                    float p3 = (key0 + 1 <= q_hi) ? __expf(s[ntk][3]) : 0.f;
                    l_lo += p0 + p1;  l_hi += p2 + p3;
                    PA[ntk >> 1][(ntk & 1) * 2]     = h2(p0, p1);
                    PA[ntk >> 1][(ntk & 1) * 2 + 1] = h2(p2, p3);
                }
#pragma unroll
                for (int ks = 0; ks < 2; ks++) {
                    u32 Vv[4];
                    LDB4(Vv, smh + H_VT, h * 16, kb * 32 + ks * 16, 136);
                    mma16a(o[0], PA[ks], Vv[0], Vv[1]);
                    mma16a(o[1], PA[ks], Vv[2], Vv[3]);
                }
            }
            l_lo += __shfl_xor_sync(0xffffffffu, l_lo, 1);
            l_lo += __shfl_xor_sync(0xffffffffu, l_lo, 2);
            l_hi += __shfl_xor_sync(0xffffffffu, l_hi, 1);
            l_hi += __shfl_xor_sync(0xffffffffu, l_hi, 2);
            const float il = __fdividef(1.f, l_lo), ih = __fdividef(1.f, l_hi);
            const int qr = qt * 16;
#pragma unroll
            for (int nv = 0; nv < 2; nv++) {
                *reinterpret_cast<u32*>(&smh[H_XN + (qr + lr)     * 40 + h*16 + nv*8 + 2*lc]) =
                    h2(o[nv][0] * il, o[nv][1] * il);
                *reinterpret_cast<u32*>(&smh[H_XN + (qr + lr + 8) * 40 + h*16 + nv*8 + 2*lc]) =
                    h2(o[nv][2] * ih, o[nv][3] * ih);
            }
        }
    }
    __syncthreads();

    // ---- stage WoT [32 c][40 j], W1t [128 j][40 d], W2t [32 c][136 j] ----
    for (int i = tid; i < 1024; i += 256) {
        int j = i >> 5, c = i & 31;
        smh[H_WB + c * 40 + j] = __float2half_rn(Wo[i]);      // i = j*32 + c
    }
    for (int i = tid; i < 4096; i += 256) {
        int d = i >> 7, j1 = i & 127;
        smh[H_QS + j1 * 40 + d] = __float2half_rn(W1[i]);     // i = d*128 + j1
        int j2 = i >> 5, c = i & 31;
        smh[H_KS + c * 136 + j2] = __float2half_rn(W2[i]);    // i = j2*32 + c
    }
    __syncthreads();

    // ================= Wo: [128,32] @ [32,32] -> OS (f32); warp = 16 rows =================
    {
        const int rb = w * 16;
        u32 A[2][4];
        LDA(A[0], smh + H_XN, rb, 0,  40);
        LDA(A[1], smh + H_XN, rb, 16, 40);
        float c[4][4];
#pragma unroll
        for (int b = 0; b < 4; b++)
#pragma unroll
            for (int q = 0; q < 4; q++) c[b][q] = 0.f;
#pragma unroll
        for (int kt = 0; kt < 2; kt++) {
#pragma unroll
            for (int n2 = 0; n2 < 2; n2++) {
                u32 Bv[4];
                LDB4(Bv, smh + H_WB, n2 * 16, kt * 16, 40);
                mma16a(c[2*n2],     A[kt], Bv[0], Bv[1]);
                mma16a(c[2*n2 + 1], A[kt], Bv[2], Bv[3]);
            }
        }
#pragma unroll
        for (int nt = 0; nt < 4; nt++) {
            *reinterpret_cast<float2*>(&smf[F_OS + (rb + lr)     * 36 + nt*8 + 2*lc]) =
                make_float2(c[nt][0], c[nt][1]);
            *reinterpret_cast<float2*>(&smf[F_OS + (rb + lr + 8) * 36 + nt*8 + 2*lc]) =
                make_float2(c[nt][2], c[nt][3]);
        }
    }
    __syncthreads();

    // ---- residual + LN2 (scalar, rows 0..127); write ZN half into XN ----
    float z[32];
    if (t < TT) {
        const float* os = smf + F_OS + t * 36;
#pragma unroll
        for (int c = 0; c < 32; c++) z[c] = xn[c] + os[c] + smf[F_BO + c];
        ln32(z, smf + F_G2, smf + F_BE2);
        u32* zr = reinterpret_cast<u32*>(smh + H_XN + t * 40);
#pragma unroll
        for (int p = 0; p < 16; p++) zr[p] = h2(z[2*p], z[2*p+1]);
    }
    __syncthreads();

    // ================= FFN: relu(ZN@W1+b1)@W2, H repacked in registers =================
    {
        const int rb = w * 16;
        u32 A[2][4];
        LDA(A[0], smh + H_XN, rb, 0,  40);
        LDA(A[1], smh + H_XN, rb, 16, 40);
        float cf[4][4];
#pragma unroll
        for (int b = 0; b < 4; b++)
#pragma unroll
            for (int q = 0; q < 4; q++) cf[b][q] = 0.f;
#pragma unroll
        for (int g = 0; g < 8; g++) {
            float hv[2][4];
#pragma unroll
            for (int b = 0; b < 2; b++)
#pragma unroll
                for (int q = 0; q < 4; q++) hv[b][q] = 0.f;
#pragma unroll
            for (int kt = 0; kt < 2; kt++) {
                u32 Bv[4];
                LDB4(Bv, smh + H_QS, g * 16, kt * 16, 40);
                mma16a(hv[0], A[kt], Bv[0], Bv[1]);
                mma16a(hv[1], A[kt], Bv[2], Bv[3]);
            }
            u32 PA[4];
#pragma unroll
            for (int ntl = 0; ntl < 2; ntl++) {
                const int nt = 2 * g + ntl;
                const float bj0 = smf[F_B1 + nt*8 + 2*lc];
                const float bj1 = smf[F_B1 + nt*8 + 2*lc + 1];
                float p0 = fmaxf(hv[ntl][0] + bj0, 0.f);
                float p1 = fmaxf(hv[ntl][1] + bj1, 0.f);
                float p2 = fmaxf(hv[ntl][2] + bj0, 0.f);
                float p3 = fmaxf(hv[ntl][3] + bj1, 0.f);
                PA[ntl * 2]     = h2(p0, p1);
                PA[ntl * 2 + 1] = h2(p2, p3);
            }
#pragma unroll
            for (int n2 = 0; n2 < 2; n2++) {
                u32 Bv[4];
                LDB4(Bv, smh + H_KS, n2 * 16, g * 16, 136);
                mma16a(cf[2*n2],     PA, Bv[0], Bv[1]);
                mma16a(cf[2*n2 + 1], PA, Bv[2], Bv[3]);
            }
        }
#pragma unroll
        for (int nt2 = 0; nt2 < 4; nt2++) {
            *reinterpret_cast<float2*>(&smf[F_OS + (rb + lr)     * 36 + nt2*8 + 2*lc]) =
                make_float2(cf[nt2][0], cf[nt2][1]);
            *reinterpret_cast<float2*>(&smf[F_OS + (rb + lr + 8) * 36 + nt2*8 + 2*lc]) =
                make_float2(cf[nt2][2], cf[nt2][3]);
        }
    }
    __syncthreads();

    // ---- final residual + store (rows 0..127) ----
    if (t < TT) {
        const float* r = smf + F_OS + t * 36;
        float4* o4 = reinterpret_cast<float4*>(out + rowbase);
#pragma unroll
        for (int c4 = 0; c4 < 8; c4++)
            o4[c4] = make_float4(z[4*c4+0] + r[4*c4+0] + smf[F_B2 + 4*c4+0],
                                 z[4*c4+1] + r[4*c4+1] + smf[F_B2 + 4*c4+1],
                                 z[4*c4+2] + r[4*c4+2] + smf[F_B2 + 4*c4+2],
                                 z[4*c4+3] + r[4*c4+3] + smf[F_B2 + 4*c4+3]);
    }
}

extern "C" void kernel_launch(void* const* d_in, const int* in_sizes, int n_in,
                              void* d_out, int out_size) {
    const float* x   = (const float*)d_in[0];
    const float* Wq  = (const float*)d_in[1];
    const float* Wk  = (const float*)d_in[2];
    const float* Wv  = (const float*)d_in[3];
    const float* Wo  = (const float*)d_in[4];
    const float* bo  = (const float*)d_in[5];
    const float* W1  = (const float*)d_in[6];
    const float* b1  = (const float*)d_in[7];
    const float* W2  = (const float*)d_in[8];
    const float* b2  = (const float*)d_in[9];
    const float* g1  = (const float*)d_in[10];
    const float* be1 = (const float*)d_in[11];
    const float* g2  = (const float*)d_in[12];
    const float* be2 = (const float*)d_in[13];

    int B = in_sizes[0] / (TT * DMM);
    cudaFuncSetAttribute(block_fused, cudaFuncAttributeMaxDynamicSharedMemorySize, SMEM_BYTES);
    block_fused<<<B, 256, SMEM_BYTES>>>(x, Wq, Wk, Wv, Wo, bo, W1, b1, W2, b2,
                                        g1, be1, g2, be2, (float*)d_out);
}